// round 5
// baseline (speedup 1.0000x reference)
#include <cuda_runtime.h>
#include <math.h>
#include <stdint.h>

#define BATCH 8192
#define INDIM 512
#define EMB   64
#define KC    256
#define DENSE 1152

// ---------------- scratch globals: separate tf32 hi/lo planes ---------------
__device__ float g_xh [BATCH * INDIM],  g_xl [BATCH * INDIM];
__device__ float g_h1h[BATCH * DENSE],  g_h1l[BATCH * DENSE];
__device__ float g_h2h[BATCH * DENSE],  g_h2l[BATCH * DENSE];
__device__ float g_ench[BATCH * EMB],   g_encl[BATCH * EMB];
__device__ float g_smph[BATCH * EMB],   g_smpl[BATCH * EMB];
__device__ float g_eW1h[DENSE * INDIM], g_eW1l[DENSE * INDIM];
__device__ float g_eW2h[DENSE * DENSE], g_eW2l[DENSE * DENSE];
__device__ float g_eW3h[EMB * DENSE],   g_eW3l[EMB * DENSE];
__device__ float g_dW1h[DENSE * EMB],   g_dW1l[DENSE * EMB];
__device__ float g_dW2h[DENSE * DENSE], g_dW2l[DENSE * DENSE];
__device__ float g_dW3h[INDIM * DENSE], g_dW3l[INDIM * DENSE];
__device__ float g_Msh[KC * EMB * EMB], g_Msl[KC * EMB * EMB];
__device__ float g_Lraw[KC * EMB * EMB];
__device__ float g_t[KC * EMB];
__device__ float g_c[KC];
__device__ float g_lpT[KC * BATCH];
__device__ int   g_idx[BATCH];

__device__ __forceinline__ float selu_f(float x) {
    const float alpha = 1.6732632423543772f;
    const float scale = 1.0507009873554805f;
    return scale * (x > 0.f ? x : alpha * expm1f(x));
}

// ---------------- ptx helpers ----------------------------------------------
__device__ __forceinline__ void cpa16(void* d, const void* s) {
    uint32_t a = (uint32_t)__cvta_generic_to_shared(d);
    asm volatile("cp.async.cg.shared.global [%0],[%1],16;" :: "r"(a), "l"(s));
}
__device__ __forceinline__ void cp_commit() { asm volatile("cp.async.commit_group;"); }
template <int N> __device__ __forceinline__ void cp_wait() {
    asm volatile("cp.async.wait_group %0;" :: "n"(N));
}
__device__ __forceinline__ void split_tf32(float v, uint32_t& hi, uint32_t& lo) {
    uint32_t h; asm("cvt.rna.tf32.f32 %0,%1;" : "=r"(h) : "f"(v));
    float r = v - __uint_as_float(h);
    uint32_t l; asm("cvt.rna.tf32.f32 %0,%1;" : "=r"(l) : "f"(r));
    hi = h; lo = l;
}
__device__ __forceinline__ void mma8(float* c, const uint32_t* a, const uint32_t* b) {
    asm volatile(
        "mma.sync.aligned.m16n8k8.row.col.f32.tf32.tf32.f32 "
        "{%0,%1,%2,%3},{%4,%5,%6,%7},{%8,%9},{%0,%1,%2,%3};"
        : "+f"(c[0]), "+f"(c[1]), "+f"(c[2]), "+f"(c[3])
        : "r"(a[0]), "r"(a[1]), "r"(a[2]), "r"(a[3]), "r"(b[0]), "r"(b[1]));
}

// ---------------- split fp32 matrix -> hi/lo planes -------------------------
__global__ void split_mat2(const float* __restrict__ src,
                           float* __restrict__ dh, float* __restrict__ dl, int n) {
    int i = blockIdx.x * blockDim.x + threadIdx.x;
    if (i < n) {
        uint32_t h, l;
        split_tf32(src[i], h, l);
        dh[i] = __uint_as_float(h);
        dl[i] = __uint_as_float(l);
    }
}

// ---------------- cluster prep ----------------------------------------------
__device__ void chol64(float (*A)[EMB + 1], float (*L)[EMB + 1], int tid) {
    __shared__ float sdiag;
    for (int j = 0; j < EMB; j++) {
        if (tid == j) {
            float s = A[j][j];
            for (int q = 0; q < j; q++) s -= L[j][q] * L[j][q];
            float d = sqrtf(fmaxf(s, 1e-30f));
            L[j][j] = d; sdiag = d;
        }
        __syncthreads();
        if (tid > j) {
            float s = A[tid][j];
            for (int q = 0; q < j; q++) s -= L[tid][q] * L[j][q];
            L[tid][j] = s / sdiag;
        }
        __syncthreads();
    }
}

__global__ void prep_clusters(const float* __restrict__ cov,
                              const float* __restrict__ means,
                              const float* __restrict__ sizes) {
    __shared__ float sA[EMB][EMB + 1];
    __shared__ float sL[EMB][EMB + 1];
    __shared__ float smu[EMB];
    const int k = blockIdx.x;
    const int tid = threadIdx.x;
    const float* Ck = cov + (size_t)k * EMB * EMB;

    for (int i = 0; i < EMB; i++) { sA[i][tid] = Ck[i * EMB + tid]; sL[i][tid] = 0.f; }
    __syncthreads();
    sA[tid][tid] += 0.005f;
    __syncthreads();
    chol64(sA, sL, tid);

    if (tid == 0) {
        float ld = 0.f;
        for (int j = 0; j < EMB; j++) ld += logf(sL[j][j]);
        g_c[k] = logf(sizes[k]) - 0.5f * (EMB * 1.8378770664093453f) - ld;
    }

    for (int i = 0; i < EMB; i++) sA[i][tid] = 0.f;
    __syncthreads();
    {
        const int c = tid;
        for (int i = c; i < EMB; i++) {
            float s = (i == c) ? 1.f : 0.f;
            for (int q = c; q < i; q++) s -= sL[i][q] * sA[q][c];
            sA[i][c] = s / sL[i][i];
        }
    }
    __syncthreads();
    // write split M rows: g_Ms{h,l}[(k*64 + r)*64 + col]
    for (int r = 0; r < EMB; r++) {
        uint32_t h, l;
        split_tf32(sA[r][tid], h, l);
        g_Msh[((size_t)k * EMB + r) * EMB + tid] = __uint_as_float(h);
        g_Msl[((size_t)k * EMB + r) * EMB + tid] = __uint_as_float(l);
    }
    smu[tid] = means[k * EMB + tid];
    __syncthreads();
    {
        float s = 0.f;
        for (int j = 0; j < EMB; j++) s += sA[tid][j] * smu[j];
        g_t[k * EMB + tid] = s;
    }
    __syncthreads();

    for (int i = 0; i < EMB; i++) { sA[i][tid] = Ck[i * EMB + tid]; sL[i][tid] = 0.f; }
    __syncthreads();
    chol64(sA, sL, tid);
    for (int r = 0; r < EMB; r++)
        g_Lraw[(size_t)k * EMB * EMB + r * EMB + tid] = sL[r][tid];
}

// ---------------- plane-split 3xTF32 GEMM -----------------------------------
// C = act(A @ W^T + bias).  A,W given as hi/lo planes (row-major, [rows][K]).
// Block: BM=32*MI rows (2 m-warps of 16*MI) x BN=32*NW cols (NW n-warps of 32).
// Conflict-free smem: each plane row-major with stride 12 (8 data + 4 pad).
template <int MI, int NW, int ACT, int SPLIT_OUT>
__global__ __launch_bounds__(64 * NW, 512 / (64 * NW)) void gemm_pl(
    const float* __restrict__ Ah, const float* __restrict__ Al,
    const float* __restrict__ Wh, const float* __restrict__ Wl,
    const float* __restrict__ bias,
    float* __restrict__ Ch, float* __restrict__ Cl,
    int M, int N, int K)
{
    constexpr int BM = 32 * MI;
    constexpr int BN = 32 * NW;
    constexpr int THREADS = 64 * NW;
    __shared__ float SA[2][2][BM * 12];
    __shared__ float SW[2][2][BN * 12];
    const int tid = threadIdx.x;
    const int lane = tid & 31, w = tid >> 5;
    const int gid = lane >> 2, tig = lane & 3;
    const int wn = w % NW, wm = w / NW;   // wm in 0..1
    const int m0 = blockIdx.y * BM, n0 = blockIdx.x * BN;

    float acc[MI][4][4];
#pragma unroll
    for (int i = 0; i < MI; i++)
#pragma unroll
        for (int j = 0; j < 4; j++)
#pragma unroll
            for (int q = 0; q < 4; q++) acc[i][j][q] = 0.f;

    auto load_stage = [&](int sb, int k0) {
#pragma unroll
        for (int f = tid; f < BM * 4; f += THREADS) {
            int r = f >> 2, pl = (f >> 1) & 1, hf = f & 1;
            cpa16(&SA[sb][pl][r * 12 + hf * 4],
                  (pl ? Al : Ah) + (size_t)(m0 + r) * K + k0 + hf * 4);
        }
#pragma unroll
        for (int f = tid; f < BN * 4; f += THREADS) {
            int r = f >> 2, pl = (f >> 1) & 1, hf = f & 1;
            cpa16(&SW[sb][pl][r * 12 + hf * 4],
                  (pl ? Wl : Wh) + (size_t)(n0 + r) * K + k0 + hf * 4);
        }
    };

    const int nst = K / 8;
    load_stage(0, 0); cp_commit();
    for (int s = 0; s < nst; s++) {
        if (s + 1 < nst) { load_stage((s + 1) & 1, (s + 1) * 8); cp_commit(); cp_wait<1>(); }
        else cp_wait<0>();
        __syncthreads();
        const int bs = s & 1;

        uint32_t bh[4][2], bl[4][2];
#pragma unroll
        for (int ni = 0; ni < 4; ni++) {
            const int rb = (wn * 32 + ni * 8 + gid) * 12;
            bh[ni][0] = __float_as_uint(SW[bs][0][rb + tig]);
            bh[ni][1] = __float_as_uint(SW[bs][0][rb + tig + 4]);
            bl[ni][0] = __float_as_uint(SW[bs][1][rb + tig]);
            bl[ni][1] = __float_as_uint(SW[bs][1][rb + tig + 4]);
        }
#pragma unroll
        for (int mi = 0; mi < MI; mi++) {
            const int ra = (wm * 16 * MI + mi * 16 + gid) * 12;
            uint32_t ah[4], al[4];
            ah[0] = __float_as_uint(SA[bs][0][ra + tig]);
            ah[1] = __float_as_uint(SA[bs][0][ra + 96 + tig]);
            ah[2] = __float_as_uint(SA[bs][0][ra + tig + 4]);
            ah[3] = __float_as_uint(SA[bs][0][ra + 96 + tig + 4]);
            al[0] = __float_as_uint(SA[bs][1][ra + tig]);
            al[1] = __float_as_uint(SA[bs][1][ra + 96 + tig]);
            al[2] = __float_as_uint(SA[bs][1][ra + tig + 4]);
            al[3] = __float_as_uint(SA[bs][1][ra + 96 + tig + 4]);
#pragma unroll
            for (int ni = 0; ni < 4; ni++) {
                mma8(acc[mi][ni], ah, bl[ni]);
                mma8(acc[mi][ni], al, bh[ni]);
                mma8(acc[mi][ni], ah, bh[ni]);
            }
        }
        __syncthreads();
    }

#pragma unroll
    for (int mi = 0; mi < MI; mi++)
#pragma unroll
        for (int ni = 0; ni < 4; ni++) {
            const int row = m0 + wm * 16 * MI + mi * 16 + gid;
            const int col = n0 + wn * 32 + ni * 8 + 2 * tig;
            const float bv0 = __ldg(bias + col), bv1 = __ldg(bias + col + 1);
            float v0 = acc[mi][ni][0] + bv0, v1 = acc[mi][ni][1] + bv1;
            float v2 = acc[mi][ni][2] + bv0, v3 = acc[mi][ni][3] + bv1;
            if (ACT) { v0 = selu_f(v0); v1 = selu_f(v1); v2 = selu_f(v2); v3 = selu_f(v3); }
            if (SPLIT_OUT) {
                uint32_t h, l;
                split_tf32(v0, h, l);
                Ch[(size_t)row * N + col] = __uint_as_float(h);
                Cl[(size_t)row * N + col] = __uint_as_float(l);
                split_tf32(v1, h, l);
                Ch[(size_t)row * N + col + 1] = __uint_as_float(h);
                Cl[(size_t)row * N + col + 1] = __uint_as_float(l);
                split_tf32(v2, h, l);
                Ch[(size_t)(row + 8) * N + col] = __uint_as_float(h);
                Cl[(size_t)(row + 8) * N + col] = __uint_as_float(l);
                split_tf32(v3, h, l);
                Ch[(size_t)(row + 8) * N + col + 1] = __uint_as_float(h);
                Cl[(size_t)(row + 8) * N + col + 1] = __uint_as_float(l);
            } else {
                *reinterpret_cast<float2*>(Ch + (size_t)row * N + col) = make_float2(v0, v1);
                *reinterpret_cast<float2*>(Ch + (size_t)(row + 8) * N + col) = make_float2(v2, v3);
            }
        }
}

// ---------------- fused quad/log_prob ---------------------------------------
// 1 cluster/block; M planes resident (stride 68: conflict-free); enc streamed.
// 8 warps: 2 m-warps (32 batch rows each, mi=2) x 4 n-warps (16 z-cols, ni=2).
__global__ __launch_bounds__(256, 2) void quad_kernel() {
    __shared__ float Msh[64 * 68], Msl[64 * 68];
    __shared__ float Esh[2][64 * 12], Esl[2][64 * 12];
    __shared__ float Ts[64];
    __shared__ float sP[64][4];
    __shared__ float cK;
    const int tid = threadIdx.x;
    const int lane = tid & 31, w = tid >> 5;
    const int gid = lane >> 2, tig = lane & 3;
    const int wn = w & 3, wm = w >> 2;
    const int k = blockIdx.x;

    // load resident M planes: 64 rows x 16 chunks x 2 planes
    for (int f = tid; f < 2048; f += 256) {
        int r = f >> 5, c = f & 31;
        int pl = c & 1, c4 = c >> 1;
        const float* src = (pl ? g_Msl : g_Msh) + ((size_t)k * 64 + r) * 64 + c4 * 4;
        float* dst = (pl ? Msl : Msh) + r * 68 + c4 * 4;
        *reinterpret_cast<float4*>(dst) = *reinterpret_cast<const float4*>(src);
    }
    if (tid < 64) Ts[tid] = g_t[k * 64 + tid];
    if (tid == 0) cK = g_c[k];
    __syncthreads();

    for (int tile = 0; tile < BATCH / 64; tile++) {
        const int b0 = tile * 64;
        float acc[2][2][4];
#pragma unroll
        for (int i = 0; i < 2; i++)
#pragma unroll
            for (int j = 0; j < 2; j++)
#pragma unroll
                for (int q = 0; q < 4; q++) acc[i][j][q] = 0.f;

        auto loadE = [&](int sb, int ck) {
            int r = tid >> 2, c = tid & 3;
            int pl = (c >> 1), hf = c & 1;
            cpa16((pl ? Esl[sb] : Esh[sb]) + r * 12 + hf * 4,
                  (pl ? g_encl : g_ench) + (size_t)(b0 + r) * 64 + ck * 8 + hf * 4);
        };
        loadE(0, 0); cp_commit();
        for (int ck = 0; ck < 8; ck++) {
            if (ck < 7) { loadE((ck + 1) & 1, ck + 1); cp_commit(); cp_wait<1>(); }
            else cp_wait<0>();
            __syncthreads();
            const int bs = ck & 1;
            uint32_t bh[2][2], bl[2][2];
#pragma unroll
            for (int ni = 0; ni < 2; ni++) {
                const int rb = (wn * 16 + ni * 8 + gid) * 68 + ck * 8;
                bh[ni][0] = __float_as_uint(Msh[rb + tig]);
                bh[ni][1] = __float_as_uint(Msh[rb + tig + 4]);
                bl[ni][0] = __float_as_uint(Msl[rb + tig]);
                bl[ni][1] = __float_as_uint(Msl[rb + tig + 4]);
            }
#pragma unroll
            for (int mi = 0; mi < 2; mi++) {
                const int ra = (wm * 32 + mi * 16 + gid) * 12;
                uint32_t ah[4], al[4];
                ah[0] = __float_as_uint(Esh[bs][ra + tig]);
                ah[1] = __float_as_uint(Esh[bs][ra + 96 + tig]);
                ah[2] = __float_as_uint(Esh[bs][ra + tig + 4]);
                ah[3] = __float_as_uint(Esh[bs][ra + 96 + tig + 4]);
                al[0] = __float_as_uint(Esl[bs][ra + tig]);
                al[1] = __float_as_uint(Esl[bs][ra + 96 + tig]);
                al[2] = __float_as_uint(Esl[bs][ra + tig + 4]);
                al[3] = __float_as_uint(Esl[bs][ra + 96 + tig + 4]);
#pragma unroll
                for (int ni = 0; ni < 2; ni++) {
                    mma8(acc[mi][ni], ah, bl[ni]);
                    mma8(acc[mi][ni], al, bh[ni]);
                    mma8(acc[mi][ni], ah, bh[ni]);
                }
            }
            __syncthreads();
        }
        // quad = sum over 64 cols of (z - t)^2
#pragma unroll
        for (int mi = 0; mi < 2; mi++)
#pragma unroll
            for (int h = 0; h < 2; h++) {
                float q = 0.f;
#pragma unroll
                for (int ni = 0; ni < 2; ni++) {
                    const int col = wn * 16 + ni * 8 + 2 * tig;
                    float z0 = acc[mi][ni][2 * h] - Ts[col];
                    float z1 = acc[mi][ni][2 * h + 1] - Ts[col + 1];
                    q = fmaf(z0, z0, fmaf(z1, z1, q));
                }
                q += __shfl_xor_sync(0xffffffffu, q, 1);
                q += __shfl_xor_sync(0xffffffffu, q, 2);
                if (tig == 0) sP[wm * 32 + mi * 16 + gid + 8 * h][wn] = q;
            }
        __syncthreads();
        if (tid < 64) {
            float lp = cK - 0.5f * (sP[tid][0] + sP[tid][1] + sP[tid][2] + sP[tid][3]);
            g_lpT[(size_t)k * BATCH + b0 + tid] = lp;
        }
        __syncthreads();
    }
}

// ---------------- transpose lpT -> out_lp [B][K] ----------------------------
__global__ void transpose_lp(float* __restrict__ out_lp) {
    __shared__ float t[32][33];
    const int bx = blockIdx.x * 32, ky = blockIdx.y * 32;
    const int tx = threadIdx.x, ty = threadIdx.y;
#pragma unroll
    for (int i = 0; i < 4; i++)
        t[ty + 8 * i][tx] = g_lpT[(size_t)(ky + ty + 8 * i) * BATCH + bx + tx];
    __syncthreads();
#pragma unroll
    for (int i = 0; i < 4; i++)
        out_lp[(size_t)(bx + ty + 8 * i) * KC + ky + tx] = t[tx][ty + 8 * i];
}

// ---------------- argmax (first-max-wins) -----------------------------------
__global__ void argmax_kernel(const float* __restrict__ lp, float* __restrict__ out_idx) {
    const int row = blockIdx.x * 8 + (threadIdx.x >> 5);
    const int lane = threadIdx.x & 31;
    float best = -3.4e38f; int bi = 0;
#pragma unroll
    for (int q = 0; q < 2; q++) {
        const int kk = lane * 4 + q * 128;
        float4 v = *reinterpret_cast<const float4*>(lp + (size_t)row * KC + kk);
        if (v.x > best) { best = v.x; bi = kk; }
        if (v.y > best) { best = v.y; bi = kk + 1; }
        if (v.z > best) { best = v.z; bi = kk + 2; }
        if (v.w > best) { best = v.w; bi = kk + 3; }
    }
#pragma unroll
    for (int o = 16; o; o >>= 1) {
        float ov = __shfl_xor_sync(0xffffffffu, best, o);
        int oi = __shfl_xor_sync(0xffffffffu, bi, o);
        if (ov > best || (ov == best && oi < bi)) { best = ov; bi = oi; }
    }
    if (lane == 0) { g_idx[row] = bi; out_idx[row] = (float)bi; }
}

// ---------------- sample = means[idx] + L_raw[idx] @ noise (split planes) ---
__global__ void sample_kernel(const float* __restrict__ means,
                              const float* __restrict__ noise) {
    __shared__ float sn[EMB];
    const int bb = blockIdx.x;
    const int i = threadIdx.x;
    sn[i] = noise[(size_t)bb * EMB + i];
    __syncthreads();
    const int k = g_idx[bb];
    const float* Lr = g_Lraw + (size_t)k * EMB * EMB + i * EMB;
    float s = means[k * EMB + i];
    for (int j = 0; j <= i; j++) s = fmaf(Lr[j], sn[j], s);
    uint32_t h, l;
    split_tf32(s, h, l);
    g_smph[(size_t)bb * EMB + i] = __uint_as_float(h);
    g_smpl[(size_t)bb * EMB + i] = __uint_as_float(l);
}

// ---------------- launch ----------------------------------------------------
extern "C" void kernel_launch(void* const* d_in, const int* in_sizes, int n_in,
                              void* d_out, int out_size) {
    const float* x     = (const float*)d_in[0];
    const float* noise = (const float*)d_in[1];
    const float* eW1 = (const float*)d_in[2];  const float* eb1 = (const float*)d_in[3];
    const float* eW2 = (const float*)d_in[4];  const float* eb2 = (const float*)d_in[5];
    const float* eW3 = (const float*)d_in[6];  const float* eb3 = (const float*)d_in[7];
    const float* dW1 = (const float*)d_in[8];  const float* db1 = (const float*)d_in[9];
    const float* dW2 = (const float*)d_in[10]; const float* db2 = (const float*)d_in[11];
    const float* dW3 = (const float*)d_in[12]; const float* db3 = (const float*)d_in[13];
    const float* means = (const float*)d_in[14];
    const float* sizes = (const float*)d_in[15];
    const float* cov   = (const float*)d_in[16];

    float* out = (float*)d_out;
    float* out_dec = out;
    float* out_lp  = out + (size_t)BATCH * INDIM;
    float* out_idx = out + (size_t)BATCH * (INDIM + KC);

    float *xh, *xl, *h1h, *h1l, *h2h, *h2l, *ench, *encl, *smph, *smpl;
    float *eW1h, *eW1l, *eW2h, *eW2l, *eW3h, *eW3l, *dW1h, *dW1l, *dW2h, *dW2l, *dW3h, *dW3l;
    cudaGetSymbolAddress((void**)&xh, g_xh);   cudaGetSymbolAddress((void**)&xl, g_xl);
    cudaGetSymbolAddress((void**)&h1h, g_h1h); cudaGetSymbolAddress((void**)&h1l, g_h1l);
    cudaGetSymbolAddress((void**)&h2h, g_h2h); cudaGetSymbolAddress((void**)&h2l, g_h2l);
    cudaGetSymbolAddress((void**)&ench, g_ench); cudaGetSymbolAddress((void**)&encl, g_encl);
    cudaGetSymbolAddress((void**)&smph, g_smph); cudaGetSymbolAddress((void**)&smpl, g_smpl);
    cudaGetSymbolAddress((void**)&eW1h, g_eW1h); cudaGetSymbolAddress((void**)&eW1l, g_eW1l);
    cudaGetSymbolAddress((void**)&eW2h, g_eW2h); cudaGetSymbolAddress((void**)&eW2l, g_eW2l);
    cudaGetSymbolAddress((void**)&eW3h, g_eW3h); cudaGetSymbolAddress((void**)&eW3l, g_eW3l);
    cudaGetSymbolAddress((void**)&dW1h, g_dW1h); cudaGetSymbolAddress((void**)&dW1l, g_dW1l);
    cudaGetSymbolAddress((void**)&dW2h, g_dW2h); cudaGetSymbolAddress((void**)&dW2l, g_dW2l);
    cudaGetSymbolAddress((void**)&dW3h, g_dW3h); cudaGetSymbolAddress((void**)&dW3l, g_dW3l);

    // pre-split x + weights into hi/lo planes
    split_mat2<<<(BATCH * INDIM + 255) / 256, 256>>>(x, xh, xl, BATCH * INDIM);
    split_mat2<<<(DENSE * INDIM + 255) / 256, 256>>>(eW1, eW1h, eW1l, DENSE * INDIM);
    split_mat2<<<(DENSE * DENSE + 255) / 256, 256>>>(eW2, eW2h, eW2l, DENSE * DENSE);
    split_mat2<<<(EMB * DENSE + 255) / 256, 256>>>(eW3, eW3h, eW3l, EMB * DENSE);
    split_mat2<<<(DENSE * EMB + 255) / 256, 256>>>(dW1, dW1h, dW1l, DENSE * EMB);
    split_mat2<<<(DENSE * DENSE + 255) / 256, 256>>>(dW2, dW2h, dW2l, DENSE * DENSE);
    split_mat2<<<(INDIM * DENSE + 255) / 256, 256>>>(dW3, dW3h, dW3l, INDIM * DENSE);

    prep_clusters<<<KC, EMB>>>(cov, means, sizes);

    // encoder
    gemm_pl<4, 4, 1, 1><<<dim3(DENSE / 128, BATCH / 128), 256>>>(
        xh, xl, eW1h, eW1l, eb1, h1h, h1l, BATCH, DENSE, INDIM);
    gemm_pl<4, 4, 1, 1><<<dim3(DENSE / 128, BATCH / 128), 256>>>(
        h1h, h1l, eW2h, eW2l, eb2, h2h, h2l, BATCH, DENSE, DENSE);
    gemm_pl<2, 2, 0, 1><<<dim3(EMB / 64, BATCH / 64), 128>>>(
        h2h, h2l, eW3h, eW3l, eb3, ench, encl, BATCH, EMB, DENSE);

    // quantize
    quad_kernel<<<KC, 256>>>();
    transpose_lp<<<dim3(BATCH / 32, KC / 32), dim3(32, 8)>>>(out_lp);
    argmax_kernel<<<BATCH / 8, 256>>>(out_lp, out_idx);
    sample_kernel<<<BATCH, EMB>>>(means, noise);

    // decoder
    gemm_pl<4, 4, 1, 1><<<dim3(DENSE / 128, BATCH / 128), 256>>>(
        smph, smpl, dW1h, dW1l, db1, h1h, h1l, BATCH, DENSE, EMB);
    gemm_pl<4, 4, 1, 1><<<dim3(DENSE / 128, BATCH / 128), 256>>>(
        h1h, h1l, dW2h, dW2l, db2, h2h, h2l, BATCH, DENSE, DENSE);
    gemm_pl<4, 4, 0, 0><<<dim3(INDIM / 128, BATCH / 128), 256>>>(
        h2h, h2l, dW3h, dW3l, db3, out_dec, nullptr, BATCH, INDIM, DENSE);
}

// round 6
// speedup vs baseline: 1.5847x; 1.5847x over previous
#include <cuda_runtime.h>
#include <cuda_fp16.h>
#include <math.h>
#include <stdint.h>

#define BATCH 8192
#define INDIM 512
#define EMB   64
#define KC    256
#define DENSE 1152

// ---------------- scratch globals: fp16 hi/lo planes ------------------------
__device__ __half g_xh [BATCH * INDIM],  g_xl [BATCH * INDIM];
__device__ __half g_h1h[BATCH * DENSE],  g_h1l[BATCH * DENSE];
__device__ __half g_h2h[BATCH * DENSE],  g_h2l[BATCH * DENSE];
__device__ __half g_ench[BATCH * EMB],   g_encl[BATCH * EMB];
__device__ __half g_smph[BATCH * EMB],   g_smpl[BATCH * EMB];
__device__ __half g_eW1h[DENSE * INDIM], g_eW1l[DENSE * INDIM];
__device__ __half g_eW2h[DENSE * DENSE], g_eW2l[DENSE * DENSE];
__device__ __half g_eW3h[EMB * DENSE],   g_eW3l[EMB * DENSE];
__device__ __half g_dW1h[DENSE * EMB],   g_dW1l[DENSE * EMB];
__device__ __half g_dW2h[DENSE * DENSE], g_dW2l[DENSE * DENSE];
__device__ __half g_dW3h[INDIM * DENSE], g_dW3l[INDIM * DENSE];
__device__ __half g_Mh[KC * EMB * EMB],  g_Ml[KC * EMB * EMB];
__device__ float g_Lraw[KC * EMB * EMB];
__device__ float g_t[KC * EMB];
__device__ float g_c[KC];
__device__ float g_lpT[KC * BATCH];
__device__ int   g_idx[BATCH];

__device__ __forceinline__ float selu_f(float x) {
    const float alpha = 1.6732632423543772f;
    const float scale = 1.0507009873554805f;
    return scale * (x > 0.f ? x : alpha * expm1f(x));
}

// ---------------- ptx helpers ----------------------------------------------
__device__ __forceinline__ void cpa16(void* d, const void* s) {
    uint32_t a = (uint32_t)__cvta_generic_to_shared(d);
    asm volatile("cp.async.cg.shared.global [%0],[%1],16;" :: "r"(a), "l"(s));
}
__device__ __forceinline__ void cp_commit() { asm volatile("cp.async.commit_group;"); }
template <int N> __device__ __forceinline__ void cp_wait() {
    asm volatile("cp.async.wait_group %0;" :: "n"(N));
}
__device__ __forceinline__ void split_h(float v, __half& h, __half& l) {
    h = __float2half_rn(v);
    l = __float2half_rn(v - __half2float(h));
}
// fp16 m16n8k16, fp32 accumulate
__device__ __forceinline__ void mma16(float* c, const uint32_t* a, const uint32_t* b) {
    asm volatile(
        "mma.sync.aligned.m16n8k16.row.col.f32.f16.f16.f32 "
        "{%0,%1,%2,%3},{%4,%5,%6,%7},{%8,%9},{%0,%1,%2,%3};"
        : "+f"(c[0]), "+f"(c[1]), "+f"(c[2]), "+f"(c[3])
        : "r"(a[0]), "r"(a[1]), "r"(a[2]), "r"(a[3]), "r"(b[0]), "r"(b[1]));
}

// ---------------- split fp32 matrix -> fp16 hi/lo planes --------------------
__global__ void split16(const float* __restrict__ src,
                        __half* __restrict__ dh, __half* __restrict__ dl, int n) {
    int i = (blockIdx.x * blockDim.x + threadIdx.x) * 2;
    if (i < n) {
        float2 v = *reinterpret_cast<const float2*>(src + i);
        __half h0, l0, h1, l1;
        split_h(v.x, h0, l0);
        split_h(v.y, h1, l1);
        *reinterpret_cast<__half2*>(dh + i) = __halves2half2(h0, h1);
        *reinterpret_cast<__half2*>(dl + i) = __halves2half2(l0, l1);
    }
}

// ---------------- cluster prep ----------------------------------------------
__device__ void chol64(float (*A)[EMB + 1], float (*L)[EMB + 1], int tid) {
    __shared__ float sdiag;
    for (int j = 0; j < EMB; j++) {
        if (tid == j) {
            float s = A[j][j];
            for (int q = 0; q < j; q++) s -= L[j][q] * L[j][q];
            float d = sqrtf(fmaxf(s, 1e-30f));
            L[j][j] = d; sdiag = d;
        }
        __syncthreads();
        if (tid > j) {
            float s = A[tid][j];
            for (int q = 0; q < j; q++) s -= L[tid][q] * L[j][q];
            L[tid][j] = s / sdiag;
        }
        __syncthreads();
    }
}

__global__ void prep_clusters(const float* __restrict__ cov,
                              const float* __restrict__ means,
                              const float* __restrict__ sizes) {
    __shared__ float sA[EMB][EMB + 1];
    __shared__ float sL[EMB][EMB + 1];
    __shared__ float smu[EMB];
    const int k = blockIdx.x;
    const int tid = threadIdx.x;
    const float* Ck = cov + (size_t)k * EMB * EMB;

    for (int i = 0; i < EMB; i++) { sA[i][tid] = Ck[i * EMB + tid]; sL[i][tid] = 0.f; }
    __syncthreads();
    sA[tid][tid] += 0.005f;
    __syncthreads();
    chol64(sA, sL, tid);

    if (tid == 0) {
        float ld = 0.f;
        for (int j = 0; j < EMB; j++) ld += logf(sL[j][j]);
        g_c[k] = logf(sizes[k]) - 0.5f * (EMB * 1.8378770664093453f) - ld;
    }

    for (int i = 0; i < EMB; i++) sA[i][tid] = 0.f;
    __syncthreads();
    {
        const int c = tid;
        for (int i = c; i < EMB; i++) {
            float s = (i == c) ? 1.f : 0.f;
            for (int q = c; q < i; q++) s -= sL[i][q] * sA[q][c];
            sA[i][c] = s / sL[i][i];
        }
    }
    __syncthreads();
    for (int r = 0; r < EMB; r++) {
        __half h, l;
        split_h(sA[r][tid], h, l);
        g_Mh[((size_t)k * EMB + r) * EMB + tid] = h;
        g_Ml[((size_t)k * EMB + r) * EMB + tid] = l;
    }
    smu[tid] = means[k * EMB + tid];
    __syncthreads();
    {
        float s = 0.f;
        for (int j = 0; j < EMB; j++) s += sA[tid][j] * smu[j];
        g_t[k * EMB + tid] = s;
    }
    __syncthreads();

    for (int i = 0; i < EMB; i++) { sA[i][tid] = Ck[i * EMB + tid]; sL[i][tid] = 0.f; }
    __syncthreads();
    chol64(sA, sL, tid);
    for (int r = 0; r < EMB; r++)
        g_Lraw[(size_t)k * EMB * EMB + r * EMB + tid] = sL[r][tid];
}

// ---------------- 2-term FP16 tensor GEMM -----------------------------------
// C = act(A @ W^T + bias).  A,W as fp16 hi/lo planes ([rows][K] row-major).
// Block: BM=64*MI x 64.  8 warps: 4 m-warps (16*MI rows) x 2 n-warps (32 cols).
// Smem plane rows: 16 data halfs + 8 pad (stride 24 halfs = 12 words) ->
// fragment lds.32 banks = 12*gid + tig (mod 32): conflict-free.
template <int MI, int ACT, int SPLIT_OUT>
__global__ __launch_bounds__(256, 2) void gemm_h(
    const __half* __restrict__ Ah, const __half* __restrict__ Al,
    const __half* __restrict__ Wh, const __half* __restrict__ Wl,
    const float* __restrict__ bias,
    __half* __restrict__ Ch, __half* __restrict__ Cl, float* __restrict__ Cf,
    int M, int N, int K)
{
    constexpr int BM = 64 * MI;
    __shared__ __half SA[2][2][BM * 24];
    __shared__ __half SW[2][2][64 * 24];
    const int tid = threadIdx.x;
    const int lane = tid & 31, w = tid >> 5;
    const int gid = lane >> 2, tig = lane & 3;
    const int wm = w >> 1, wn = w & 1;
    const int m0 = blockIdx.y * BM, n0 = blockIdx.x * 64;

    float acc[MI][4][4];
#pragma unroll
    for (int i = 0; i < MI; i++)
#pragma unroll
        for (int j = 0; j < 4; j++)
#pragma unroll
            for (int q = 0; q < 4; q++) acc[i][j][q] = 0.f;

    auto load_stage = [&](int sb, int k0) {
#pragma unroll
        for (int f = tid; f < BM * 4; f += 256) {
            int r = f >> 2, pl = (f >> 1) & 1, hf = f & 1;
            cpa16(&SA[sb][pl][r * 24 + hf * 8],
                  (pl ? Al : Ah) + (size_t)(m0 + r) * K + k0 + hf * 8);
        }
        {
            int r = tid >> 2, pl = (tid >> 1) & 1, hf = tid & 1;
            cpa16(&SW[sb][pl][r * 24 + hf * 8],
                  (pl ? Wl : Wh) + (size_t)(n0 + r) * K + k0 + hf * 8);
        }
    };

    const int nst = K / 16;
    load_stage(0, 0); cp_commit();
    for (int s = 0; s < nst; s++) {
        if (s + 1 < nst) { load_stage((s + 1) & 1, (s + 1) * 16); cp_commit(); cp_wait<1>(); }
        else cp_wait<0>();
        __syncthreads();
        const int bs = s & 1;

        uint32_t bh[4][2], bl[4][2];
#pragma unroll
        for (int ni = 0; ni < 4; ni++) {
            const int rb = (wn * 32 + ni * 8 + gid) * 24 + 2 * tig;
            bh[ni][0] = *reinterpret_cast<const uint32_t*>(&SW[bs][0][rb]);
            bh[ni][1] = *reinterpret_cast<const uint32_t*>(&SW[bs][0][rb + 8]);
            bl[ni][0] = *reinterpret_cast<const uint32_t*>(&SW[bs][1][rb]);
            bl[ni][1] = *reinterpret_cast<const uint32_t*>(&SW[bs][1][rb + 8]);
        }
#pragma unroll
        for (int mi = 0; mi < MI; mi++) {
            const int ra = (wm * 16 * MI + mi * 16 + gid) * 24 + 2 * tig;
            uint32_t ah[4], al[4];
            ah[0] = *reinterpret_cast<const uint32_t*>(&SA[bs][0][ra]);
            ah[1] = *reinterpret_cast<const uint32_t*>(&SA[bs][0][ra + 192]);
            ah[2] = *reinterpret_cast<const uint32_t*>(&SA[bs][0][ra + 8]);
            ah[3] = *reinterpret_cast<const uint32_t*>(&SA[bs][0][ra + 200]);
            al[0] = *reinterpret_cast<const uint32_t*>(&SA[bs][1][ra]);
            al[1] = *reinterpret_cast<const uint32_t*>(&SA[bs][1][ra + 192]);
            al[2] = *reinterpret_cast<const uint32_t*>(&SA[bs][1][ra + 8]);
            al[3] = *reinterpret_cast<const uint32_t*>(&SA[bs][1][ra + 200]);
#pragma unroll
            for (int ni = 0; ni < 4; ni++) {
                mma16(acc[mi][ni], ah, bl[ni]);
                mma16(acc[mi][ni], al, bh[ni]);
                mma16(acc[mi][ni], ah, bh[ni]);
            }
        }
        __syncthreads();
    }

#pragma unroll
    for (int mi = 0; mi < MI; mi++)
#pragma unroll
        for (int ni = 0; ni < 4; ni++) {
            const int row = m0 + wm * 16 * MI + mi * 16 + gid;
            const int col = n0 + wn * 32 + ni * 8 + 2 * tig;
            const float bv0 = __ldg(bias + col), bv1 = __ldg(bias + col + 1);
            float v0 = acc[mi][ni][0] + bv0, v1 = acc[mi][ni][1] + bv1;
            float v2 = acc[mi][ni][2] + bv0, v3 = acc[mi][ni][3] + bv1;
            if (ACT) { v0 = selu_f(v0); v1 = selu_f(v1); v2 = selu_f(v2); v3 = selu_f(v3); }
            if (SPLIT_OUT) {
                __half h0, l0, h1, l1;
                split_h(v0, h0, l0); split_h(v1, h1, l1);
                *reinterpret_cast<__half2*>(Ch + (size_t)row * N + col) = __halves2half2(h0, h1);
                *reinterpret_cast<__half2*>(Cl + (size_t)row * N + col) = __halves2half2(l0, l1);
                split_h(v2, h0, l0); split_h(v3, h1, l1);
                *reinterpret_cast<__half2*>(Ch + (size_t)(row + 8) * N + col) = __halves2half2(h0, h1);
                *reinterpret_cast<__half2*>(Cl + (size_t)(row + 8) * N + col) = __halves2half2(l0, l1);
            } else {
                *reinterpret_cast<float2*>(Cf + (size_t)row * N + col) = make_float2(v0, v1);
                *reinterpret_cast<float2*>(Cf + (size_t)(row + 8) * N + col) = make_float2(v2, v3);
            }
        }
}

// ---------------- fused quad/log_prob (fp16 2-term) -------------------------
// 1 cluster/block; M hi/lo planes resident (row stride 72 halfs = 36 words ->
// banks 4*gid + tig: conflict-free); enc streamed.
// 8 warps: 2 m-warps (32 batch rows, mi=2) x 4 n-warps (16 z-cols, ni=2).
__global__ __launch_bounds__(256, 2) void quad_kernel() {
    __shared__ __half Mh[64 * 72], Ml[64 * 72];
    __shared__ __half Eh[2][64 * 24], El[2][64 * 24];
    __shared__ float Ts[64];
    __shared__ float sP[64][4];
    __shared__ float cK;
    const int tid = threadIdx.x;
    const int lane = tid & 31, w = tid >> 5;
    const int gid = lane >> 2, tig = lane & 3;
    const int wn = w & 3, wm = w >> 2;
    const int k = blockIdx.x;

    // resident M planes: 64 rows x 8 chunks(16B) x 2 planes = 1024 chunks
    for (int f = tid; f < 1024; f += 256) {
        int pl = f & 1, g = f >> 1;
        int r = g >> 3, ch = g & 7;
        const __half* src = (pl ? g_Ml : g_Mh) + ((size_t)k * 64 + r) * 64 + ch * 8;
        __half* dst = (pl ? Ml : Mh) + r * 72 + ch * 8;
        *reinterpret_cast<float4*>(dst) = *reinterpret_cast<const float4*>(src);
    }
    if (tid < 64) Ts[tid] = g_t[k * 64 + tid];
    if (tid == 0) cK = g_c[k];
    __syncthreads();

    for (int tile = 0; tile < BATCH / 64; tile++) {
        const int b0 = tile * 64;
        float acc[2][2][4];
#pragma unroll
        for (int i = 0; i < 2; i++)
#pragma unroll
            for (int j = 0; j < 2; j++)
#pragma unroll
                for (int q = 0; q < 4; q++) acc[i][j][q] = 0.f;

        auto loadE = [&](int sb, int ck) {
            int r = tid >> 2, pl = (tid >> 1) & 1, hf = tid & 1;
            cpa16((pl ? El[sb] : Eh[sb]) + r * 24 + hf * 8,
                  (pl ? g_encl : g_ench) + (size_t)(b0 + r) * 64 + ck * 16 + hf * 8);
        };
        loadE(0, 0); cp_commit();
        for (int ck = 0; ck < 4; ck++) {
            if (ck < 3) { loadE((ck + 1) & 1, ck + 1); cp_commit(); cp_wait<1>(); }
            else cp_wait<0>();
            __syncthreads();
            const int bs = ck & 1;
            uint32_t bh[2][2], bl[2][2];
#pragma unroll
            for (int ni = 0; ni < 2; ni++) {
                const int rb = (wn * 16 + ni * 8 + gid) * 72 + ck * 16 + 2 * tig;
                bh[ni][0] = *reinterpret_cast<const uint32_t*>(&Mh[rb]);
                bh[ni][1] = *reinterpret_cast<const uint32_t*>(&Mh[rb + 8]);
                bl[ni][0] = *reinterpret_cast<const uint32_t*>(&Ml[rb]);
                bl[ni][1] = *reinterpret_cast<const uint32_t*>(&Ml[rb + 8]);
            }
#pragma unroll
            for (int mi = 0; mi < 2; mi++) {
                const int ra = (wm * 32 + mi * 16 + gid) * 24 + 2 * tig;
                uint32_t ah[4], al[4];
                ah[0] = *reinterpret_cast<const uint32_t*>(&Eh[bs][ra]);
                ah[1] = *reinterpret_cast<const uint32_t*>(&Eh[bs][ra + 192]);
                ah[2] = *reinterpret_cast<const uint32_t*>(&Eh[bs][ra + 8]);
                ah[3] = *reinterpret_cast<const uint32_t*>(&Eh[bs][ra + 200]);
                al[0] = *reinterpret_cast<const uint32_t*>(&El[bs][ra]);
                al[1] = *reinterpret_cast<const uint32_t*>(&El[bs][ra + 192]);
                al[2] = *reinterpret_cast<const uint32_t*>(&El[bs][ra + 8]);
                al[3] = *reinterpret_cast<const uint32_t*>(&El[bs][ra + 200]);
#pragma unroll
                for (int ni = 0; ni < 2; ni++) {
                    mma16(acc[mi][ni], ah, bl[ni]);
                    mma16(acc[mi][ni], al, bh[ni]);
                    mma16(acc[mi][ni], ah, bh[ni]);
                }
            }
            __syncthreads();
        }
        // quad = sum over 64 z-cols of (z - t)^2
#pragma unroll
        for (int mi = 0; mi < 2; mi++)
#pragma unroll
            for (int h = 0; h < 2; h++) {
                float q = 0.f;
#pragma unroll
                for (int ni = 0; ni < 2; ni++) {
                    const int col = wn * 16 + ni * 8 + 2 * tig;
                    float z0 = acc[mi][ni][2 * h] - Ts[col];
                    float z1 = acc[mi][ni][2 * h + 1] - Ts[col + 1];
                    q = fmaf(z0, z0, fmaf(z1, z1, q));
                }
                q += __shfl_xor_sync(0xffffffffu, q, 1);
                q += __shfl_xor_sync(0xffffffffu, q, 2);
                if (tig == 0) sP[wm * 32 + mi * 16 + gid + 8 * h][wn] = q;
            }
        __syncthreads();
        if (tid < 64) {
            float lp = cK - 0.5f * (sP[tid][0] + sP[tid][1] + sP[tid][2] + sP[tid][3]);
            g_lpT[(size_t)k * BATCH + b0 + tid] = lp;
        }
        __syncthreads();
    }
}

// ---------------- transpose lpT -> out_lp [B][K] ----------------------------
__global__ void transpose_lp(float* __restrict__ out_lp) {
    __shared__ float t[32][33];
    const int bx = blockIdx.x * 32, ky = blockIdx.y * 32;
    const int tx = threadIdx.x, ty = threadIdx.y;
#pragma unroll
    for (int i = 0; i < 4; i++)
        t[ty + 8 * i][tx] = g_lpT[(size_t)(ky + ty + 8 * i) * BATCH + bx + tx];
    __syncthreads();
#pragma unroll
    for (int i = 0; i < 4; i++)
        out_lp[(size_t)(bx + ty + 8 * i) * KC + ky + tx] = t[tx][ty + 8 * i];
}

// ---------------- argmax (first-max-wins) -----------------------------------
__global__ void argmax_kernel(const float* __restrict__ lp, float* __restrict__ out_idx) {
    const int row = blockIdx.x * 8 + (threadIdx.x >> 5);
    const int lane = threadIdx.x & 31;
    float best = -3.4e38f; int bi = 0;
#pragma unroll
    for (int q = 0; q < 2; q++) {
        const int kk = lane * 4 + q * 128;
        float4 v = *reinterpret_cast<const float4*>(lp + (size_t)row * KC + kk);
        if (v.x > best) { best = v.x; bi = kk; }
        if (v.y > best) { best = v.y; bi = kk + 1; }
        if (v.z > best) { best = v.z; bi = kk + 2; }
        if (v.w > best) { best = v.w; bi = kk + 3; }
    }
#pragma unroll
    for (int o = 16; o; o >>= 1) {
        float ov = __shfl_xor_sync(0xffffffffu, best, o);
        int oi = __shfl_xor_sync(0xffffffffu, bi, o);
        if (ov > best || (ov == best && oi < bi)) { best = ov; bi = oi; }
    }
    if (lane == 0) { g_idx[row] = bi; out_idx[row] = (float)bi; }
}

// ---------------- sample = means[idx] + L_raw[idx] @ noise ------------------
__global__ void sample_kernel(const float* __restrict__ means,
                              const float* __restrict__ noise) {
    __shared__ float sn[EMB];
    const int bb = blockIdx.x;
    const int i = threadIdx.x;
    sn[i] = noise[(size_t)bb * EMB + i];
    __syncthreads();
    const int k = g_idx[bb];
    const float* Lr = g_Lraw + (size_t)k * EMB * EMB + i * EMB;
    float s = means[k * EMB + i];
    for (int j = 0; j <= i; j++) s = fmaf(Lr[j], sn[j], s);
    __half h, l;
    split_h(s, h, l);
    g_smph[(size_t)bb * EMB + i] = h;
    g_smpl[(size_t)bb * EMB + i] = l;
}

// ---------------- launch ----------------------------------------------------
extern "C" void kernel_launch(void* const* d_in, const int* in_sizes, int n_in,
                              void* d_out, int out_size) {
    const float* x     = (const float*)d_in[0];
    const float* noise = (const float*)d_in[1];
    const float* eW1 = (const float*)d_in[2];  const float* eb1 = (const float*)d_in[3];
    const float* eW2 = (const float*)d_in[4];  const float* eb2 = (const float*)d_in[5];
    const float* eW3 = (const float*)d_in[6];  const float* eb3 = (const float*)d_in[7];
    const float* dW1 = (const float*)d_in[8];  const float* db1 = (const float*)d_in[9];
    const float* dW2 = (const float*)d_in[10]; const float* db2 = (const float*)d_in[11];
    const float* dW3 = (const float*)d_in[12]; const float* db3 = (const float*)d_in[13];
    const float* means = (const float*)d_in[14];
    const float* sizes = (const float*)d_in[15];
    const float* cov   = (const float*)d_in[16];

    float* out = (float*)d_out;
    float* out_dec = out;
    float* out_lp  = out + (size_t)BATCH * INDIM;
    float* out_idx = out + (size_t)BATCH * (INDIM + KC);

    __half *xh, *xl, *h1h, *h1l, *h2h, *h2l, *ench, *encl, *smph, *smpl;
    __half *eW1h, *eW1l, *eW2h, *eW2l, *eW3h, *eW3l, *dW1h, *dW1l, *dW2h, *dW2l, *dW3h, *dW3l;
    cudaGetSymbolAddress((void**)&xh, g_xh);   cudaGetSymbolAddress((void**)&xl, g_xl);
    cudaGetSymbolAddress((void**)&h1h, g_h1h); cudaGetSymbolAddress((void**)&h1l, g_h1l);
    cudaGetSymbolAddress((void**)&h2h, g_h2h); cudaGetSymbolAddress((void**)&h2l, g_h2l);
    cudaGetSymbolAddress((void**)&ench, g_ench); cudaGetSymbolAddress((void**)&encl, g_encl);
    cudaGetSymbolAddress((void**)&smph, g_smph); cudaGetSymbolAddress((void**)&smpl, g_smpl);
    cudaGetSymbolAddress((void**)&eW1h, g_eW1h); cudaGetSymbolAddress((void**)&eW1l, g_eW1l);
    cudaGetSymbolAddress((void**)&eW2h, g_eW2h); cudaGetSymbolAddress((void**)&eW2l, g_eW2l);
    cudaGetSymbolAddress((void**)&eW3h, g_eW3h); cudaGetSymbolAddress((void**)&eW3l, g_eW3l);
    cudaGetSymbolAddress((void**)&dW1h, g_dW1h); cudaGetSymbolAddress((void**)&dW1l, g_dW1l);
    cudaGetSymbolAddress((void**)&dW2h, g_dW2h); cudaGetSymbolAddress((void**)&dW2l, g_dW2l);
    cudaGetSymbolAddress((void**)&dW3h, g_dW3h); cudaGetSymbolAddress((void**)&dW3l, g_dW3l);

    // pre-split x + weights into fp16 hi/lo planes
    split16<<<(BATCH * INDIM / 2 + 255) / 256, 256>>>(x, xh, xl, BATCH * INDIM);
    split16<<<(DENSE * INDIM / 2 + 255) / 256, 256>>>(eW1, eW1h, eW1l, DENSE * INDIM);
    split16<<<(DENSE * DENSE / 2 + 255) / 256, 256>>>(eW2, eW2h, eW2l, DENSE * DENSE);
    split16<<<(EMB * DENSE / 2 + 255) / 256, 256>>>(eW3, eW3h, eW3l, EMB * DENSE);
    split16<<<(DENSE * EMB / 2 + 255) / 256, 256>>>(dW1, dW1h, dW1l, DENSE * EMB);
    split16<<<(DENSE * DENSE / 2 + 255) / 256, 256>>>(dW2, dW2h, dW2l, DENSE * DENSE);
    split16<<<(INDIM * DENSE / 2 + 255) / 256, 256>>>(dW3, dW3h, dW3l, INDIM * DENSE);

    prep_clusters<<<KC, EMB>>>(cov, means, sizes);

    // encoder
    gemm_h<2, 1, 1><<<dim3(DENSE / 64, BATCH / 128), 256>>>(
        xh, xl, eW1h, eW1l, eb1, h1h, h1l, nullptr, BATCH, DENSE, INDIM);
    gemm_h<2, 1, 1><<<dim3(DENSE / 64, BATCH / 128), 256>>>(
        h1h, h1l, eW2h, eW2l, eb2, h2h, h2l, nullptr, BATCH, DENSE, DENSE);
    gemm_h<1, 0, 1><<<dim3(EMB / 64, BATCH / 64), 256>>>(
        h2h, h2l, eW3h, eW3l, eb3, ench, encl, nullptr, BATCH, EMB, DENSE);

    // quantize
    quad_kernel<<<KC, 256>>>();
    transpose_lp<<<dim3(BATCH / 32, KC / 32), dim3(32, 8)>>>(out_lp);
    argmax_kernel<<<BATCH / 8, 256>>>(out_lp, out_idx);
    sample_kernel<<<BATCH, EMB>>>(means, noise);

    // decoder
    gemm_h<2, 1, 1><<<dim3(DENSE / 64, BATCH / 128), 256>>>(
        smph, smpl, dW1h, dW1l, db1, h1h, h1l, nullptr, BATCH, DENSE, EMB);
    gemm_h<2, 1, 1><<<dim3(DENSE / 64, BATCH / 128), 256>>>(
        h1h, h1l, dW2h, dW2l, db2, h2h, h2l, nullptr, BATCH, DENSE, DENSE);
    gemm_h<2, 0, 0><<<dim3(INDIM / 64, BATCH / 128), 256>>>(
        h2h, h2l, dW3h, dW3l, db3, nullptr, nullptr, out_dec, BATCH, INDIM, DENSE);
}

// round 9
// speedup vs baseline: 2.0360x; 1.2848x over previous
#include <cuda_runtime.h>
#include <cuda_fp16.h>
#include <math.h>
#include <stdint.h>

#define BATCH 8192
#define INDIM 512
#define EMB   64
#define KC    256
#define DENSE 1152

// ---------------- scratch globals: fp16 hi/lo planes ------------------------
__device__ __half g_xh [BATCH * INDIM],  g_xl [BATCH * INDIM];
__device__ __half g_h1h[BATCH * DENSE],  g_h1l[BATCH * DENSE];
__device__ __half g_h2h[BATCH * DENSE],  g_h2l[BATCH * DENSE];
__device__ __half g_ench[BATCH * EMB],   g_encl[BATCH * EMB];
__device__ __half g_smph[BATCH * EMB],   g_smpl[BATCH * EMB];
__device__ __half g_eW1h[DENSE * INDIM], g_eW1l[DENSE * INDIM];
__device__ __half g_eW2h[DENSE * DENSE], g_eW2l[DENSE * DENSE];
__device__ __half g_eW3h[EMB * DENSE],   g_eW3l[EMB * DENSE];
__device__ __half g_dW1h[DENSE * EMB],   g_dW1l[DENSE * EMB];
__device__ __half g_dW2h[DENSE * DENSE], g_dW2l[DENSE * DENSE];
__device__ __half g_dW3h[INDIM * DENSE], g_dW3l[INDIM * DENSE];
__device__ __half g_Mh[KC * EMB * EMB],  g_Ml[KC * EMB * EMB];
__device__ float g_Lraw[KC * EMB * EMB];
__device__ float g_t[KC * EMB];
__device__ float g_c[KC];
__device__ float g_lpT[KC * BATCH];
__device__ int   g_idx[BATCH];

__device__ __forceinline__ float selu_f(float x) {
    const float alpha = 1.6732632423543772f;
    const float scale = 1.0507009873554805f;
    return scale * (x > 0.f ? x : alpha * expm1f(x));
}

// ---------------- ptx helpers ----------------------------------------------
__device__ __forceinline__ void cpa16(void* d, const void* s) {
    uint32_t a = (uint32_t)__cvta_generic_to_shared(d);
    asm volatile("cp.async.cg.shared.global [%0],[%1],16;" :: "r"(a), "l"(s));
}
__device__ __forceinline__ void cp_commit() { asm volatile("cp.async.commit_group;"); }
template <int N> __device__ __forceinline__ void cp_wait() {
    asm volatile("cp.async.wait_group %0;" :: "n"(N));
}
__device__ __forceinline__ void split_h(float v, __half& h, __half& l) {
    h = __float2half_rn(v);
    l = __float2half_rn(v - __half2float(h));
}
__device__ __forceinline__ void mma16(float* c, const uint32_t* a, const uint32_t* b) {
    asm volatile(
        "mma.sync.aligned.m16n8k16.row.col.f32.f16.f16.f32 "
        "{%0,%1,%2,%3},{%4,%5,%6,%7},{%8,%9},{%0,%1,%2,%3};"
        : "+f"(c[0]), "+f"(c[1]), "+f"(c[2]), "+f"(c[3])
        : "r"(a[0]), "r"(a[1]), "r"(a[2]), "r"(a[3]), "r"(b[0]), "r"(b[1]));
}
__device__ __forceinline__ uint32_t ldh32(const __half* p) {
    return *reinterpret_cast<const uint32_t*>(p);
}

// ---------------- split fp32 matrix -> fp16 hi/lo planes --------------------
__global__ void split16(const float* __restrict__ src,
                        __half* __restrict__ dh, __half* __restrict__ dl, int n) {
    int i = (blockIdx.x * blockDim.x + threadIdx.x) * 2;
    if (i < n) {
        float2 v = *reinterpret_cast<const float2*>(src + i);
        __half h0, l0, h1, l1;
        split_h(v.x, h0, l0);
        split_h(v.y, h1, l1);
        *reinterpret_cast<__half2*>(dh + i) = __halves2half2(h0, h1);
        *reinterpret_cast<__half2*>(dl + i) = __halves2half2(l0, l1);
    }
}

// ---------------- cluster prep ----------------------------------------------
__device__ void chol64(float (*A)[EMB + 1], float (*L)[EMB + 1], int tid) {
    __shared__ float sdiag;
    for (int j = 0; j < EMB; j++) {
        if (tid == j) {
            float s = A[j][j];
            for (int q = 0; q < j; q++) s -= L[j][q] * L[j][q];
            float d = sqrtf(fmaxf(s, 1e-30f));
            L[j][j] = d; sdiag = d;
        }
        __syncthreads();
        if (tid > j) {
            float s = A[tid][j];
            for (int q = 0; q < j; q++) s -= L[tid][q] * L[j][q];
            L[tid][j] = s / sdiag;
        }
        __syncthreads();
    }
}

__global__ void prep_clusters(const float* __restrict__ cov,
                              const float* __restrict__ means,
                              const float* __restrict__ sizes) {
    __shared__ float sA[EMB][EMB + 1];
    __shared__ float sL[EMB][EMB + 1];
    __shared__ float smu[EMB];
    const int k = blockIdx.x;
    const int tid = threadIdx.x;
    const float* Ck = cov + (size_t)k * EMB * EMB;

    for (int i = 0; i < EMB; i++) { sA[i][tid] = Ck[i * EMB + tid]; sL[i][tid] = 0.f; }
    __syncthreads();
    sA[tid][tid] += 0.005f;
    __syncthreads();
    chol64(sA, sL, tid);

    if (tid == 0) {
        float ld = 0.f;
        for (int j = 0; j < EMB; j++) ld += logf(sL[j][j]);
        g_c[k] = logf(sizes[k]) - 0.5f * (EMB * 1.8378770664093453f) - ld;
    }

    for (int i = 0; i < EMB; i++) sA[i][tid] = 0.f;
    __syncthreads();
    {
        const int c = tid;
        for (int i = c; i < EMB; i++) {
            float s = (i == c) ? 1.f : 0.f;
            for (int q = c; q < i; q++) s -= sL[i][q] * sA[q][c];
            sA[i][c] = s / sL[i][i];
        }
    }
    __syncthreads();
    for (int r = 0; r < EMB; r++) {
        __half h, l;
        split_h(sA[r][tid], h, l);
        g_Mh[((size_t)k * EMB + r) * EMB + tid] = h;
        g_Ml[((size_t)k * EMB + r) * EMB + tid] = l;
    }
    smu[tid] = means[k * EMB + tid];
    __syncthreads();
    {
        float s = 0.f;
        for (int j = 0; j < EMB; j++) s += sA[tid][j] * smu[j];
        g_t[k * EMB + tid] = s;
    }
    __syncthreads();

    for (int i = 0; i < EMB; i++) { sA[i][tid] = Ck[i * EMB + tid]; sL[i][tid] = 0.f; }
    __syncthreads();
    chol64(sA, sL, tid);
    for (int r = 0; r < EMB; r++)
        g_Lraw[(size_t)k * EMB * EMB + r * EMB + tid] = sL[r][tid];
}

// ---------------- split-fp16 tensor GEMM (mma.sync), K-chunk 32 -------------
// C = act(A @ W^T + bias).  Block BM=64*MI x 64; 8 warps: 4m x 2n, warp 16*MI x 32.
// TERMS=3: acc = ah*bh + ah*bl + al*bh (full 2-term split both sides).
// TERMS=2: acc = ah*bh + ah*bl (A hi-only; ~2^-11 relative error).
// Smem rows: 32 data halfs + 8 pad (stride 40 halfs = 20 words -> banks
// 20*gid + tig mod 32: all distinct, conflict-free).
template <int MI, int TERMS, int ACT, int SPLIT_OUT>
__global__ __launch_bounds__(256) void gemm_h(
    const __half* __restrict__ Ah, const __half* __restrict__ Al,
    const __half* __restrict__ Wh, const __half* __restrict__ Wl,
    const float* __restrict__ bias,
    __half* __restrict__ Ch, __half* __restrict__ Cl, float* __restrict__ Cf,
    int M, int N, int K)
{
    constexpr int BM = 64 * MI;
    constexpr int PA = (TERMS == 3) ? 2 : 1;
    extern __shared__ __half sh[];
    __half* SA = sh;                       // [2][PA][BM*40]
    __half* SW = sh + 2 * PA * BM * 40;    // [2][2][64*40]
    const int tid = threadIdx.x;
    const int lane = tid & 31, w = tid >> 5;
    const int gid = lane >> 2, tig = lane & 3;
    const int wm = w >> 1, wn = w & 1;
    const int m0 = blockIdx.y * BM, n0 = blockIdx.x * 64;

    float acc[MI][4][4];
#pragma unroll
    for (int i = 0; i < MI; i++)
#pragma unroll
        for (int j = 0; j < 4; j++)
#pragma unroll
            for (int q = 0; q < 4; q++) acc[i][j][q] = 0.f;

    auto fill = [&](int s, int k0) {
#pragma unroll
        for (int q = 0; q < PA * BM / 64; q++) {
            int u = tid + q * 256;
            int pl = u / (BM * 4), rem = u % (BM * 4);
            int r = rem >> 2, c8 = (rem & 3) * 8;
            cpa16(&SA[((size_t)(s * PA + pl) * BM + r) * 40 + c8],
                  (pl ? Al : Ah) + (size_t)(m0 + r) * K + k0 + c8);
        }
#pragma unroll
        for (int q = 0; q < 2; q++) {
            int u = tid + q * 256;
            int pl = u >> 8, rem = u & 255;
            int r = rem >> 2, c8 = (rem & 3) * 8;
            cpa16(&SW[((size_t)(s * 2 + pl) * 64 + r) * 40 + c8],
                  (pl ? Wl : Wh) + (size_t)(n0 + r) * K + k0 + c8);
        }
    };

    const int nst = K / 32;
    fill(0, 0); cp_commit();
    for (int s = 0; s < nst; s++) {
        if (s + 1 < nst) { fill((s + 1) & 1, (s + 1) * 32); cp_commit(); cp_wait<1>(); }
        else cp_wait<0>();
        __syncthreads();
        const int bs = s & 1;
#pragma unroll
        for (int kk = 0; kk < 32; kk += 16) {
            uint32_t bh[4][2], bl[4][2];
#pragma unroll
            for (int ni = 0; ni < 4; ni++) {
                const int rb = wn * 32 + ni * 8 + gid;
                const int ph = ((bs * 2 + 0) * 64 + rb) * 40 + kk + 2 * tig;
                const int pl_ = ((bs * 2 + 1) * 64 + rb) * 40 + kk + 2 * tig;
                bh[ni][0] = ldh32(&SW[ph]);   bh[ni][1] = ldh32(&SW[ph + 8]);
                bl[ni][0] = ldh32(&SW[pl_]);  bl[ni][1] = ldh32(&SW[pl_ + 8]);
            }
#pragma unroll
            for (int mi = 0; mi < MI; mi++) {
                const int rowa = wm * 16 * MI + mi * 16 + gid;
                const int pa = ((bs * PA + 0) * BM + rowa) * 40 + kk + 2 * tig;
                uint32_t ah[4];
                ah[0] = ldh32(&SA[pa]);       ah[1] = ldh32(&SA[pa + 320]);
                ah[2] = ldh32(&SA[pa + 8]);   ah[3] = ldh32(&SA[pa + 328]);
                if (TERMS == 3) {
                    const int pb = ((bs * PA + 1) * BM + rowa) * 40 + kk + 2 * tig;
                    uint32_t al[4];
                    al[0] = ldh32(&SA[pb]);     al[1] = ldh32(&SA[pb + 320]);
                    al[2] = ldh32(&SA[pb + 8]); al[3] = ldh32(&SA[pb + 328]);
#pragma unroll
                    for (int ni = 0; ni < 4; ni++) {
                        mma16(acc[mi][ni], ah, bl[ni]);
                        mma16(acc[mi][ni], al, bh[ni]);
                        mma16(acc[mi][ni], ah, bh[ni]);
                    }
                } else {
#pragma unroll
                    for (int ni = 0; ni < 4; ni++) {
                        mma16(acc[mi][ni], ah, bl[ni]);
                        mma16(acc[mi][ni], ah, bh[ni]);
                    }
                }
            }
        }
        __syncthreads();
    }

#pragma unroll
    for (int mi = 0; mi < MI; mi++)
#pragma unroll
        for (int ni = 0; ni < 4; ni++) {
            const int row = m0 + wm * 16 * MI + mi * 16 + gid;
            const int col = n0 + wn * 32 + ni * 8 + 2 * tig;
            const float bv0 = __ldg(bias + col), bv1 = __ldg(bias + col + 1);
            float v0 = acc[mi][ni][0] + bv0, v1 = acc[mi][ni][1] + bv1;
            float v2 = acc[mi][ni][2] + bv0, v3 = acc[mi][ni][3] + bv1;
            if (ACT) { v0 = selu_f(v0); v1 = selu_f(v1); v2 = selu_f(v2); v3 = selu_f(v3); }
            if (SPLIT_OUT) {
                __half h0, l0, h1, l1;
                split_h(v0, h0, l0); split_h(v1, h1, l1);
                *reinterpret_cast<__half2*>(Ch + (size_t)row * N + col) = __halves2half2(h0, h1);
                *reinterpret_cast<__half2*>(Cl + (size_t)row * N + col) = __halves2half2(l0, l1);
                split_h(v2, h0, l0); split_h(v3, h1, l1);
                *reinterpret_cast<__half2*>(Ch + (size_t)(row + 8) * N + col) = __halves2half2(h0, h1);
                *reinterpret_cast<__half2*>(Cl + (size_t)(row + 8) * N + col) = __halves2half2(l0, l1);
            } else {
                *reinterpret_cast<float2*>(Cf + (size_t)row * N + col) = make_float2(v0, v1);
                *reinterpret_cast<float2*>(Cf + (size_t)(row + 8) * N + col) = make_float2(v2, v3);
            }
        }
}

// ---------------- fused quad/log_prob: 2 clusters/block ----------------------
// M (128 rows = 2 clusters x 64, hi/lo, stride 72 halfs -> banks 4*gid+tig,
// conflict-free) resident; enc streamed in 32-half chunks (stride 40).
// 8 warps: 2 m-warps (32 rows each, mi=2) x 4 n-warps (32 cols each, ni=4).
__global__ __launch_bounds__(256) void quad_kernel() {
    extern __shared__ __half qsh[];
    __half* Mhs = qsh;                   // [128][72]
    __half* Mls = qsh + 128 * 72;
    __half* Ehs = qsh + 2 * 128 * 72;    // [2][64*40]
    __half* Els = Ehs + 2 * 64 * 40;
    float*  Ts  = (float*)(Els + 2 * 64 * 40);  // [128]
    float*  sP  = Ts + 128;                     // [64][4]
    float*  cK  = sP + 256;                     // [2]
    const int tid = threadIdx.x;
    const int lane = tid & 31, w = tid >> 5;
    const int gid = lane >> 2, tig = lane & 3;
    const int wn = w & 3, wm = w >> 2;
    const int kc0 = blockIdx.x * 2;

    for (int f = tid; f < 2048; f += 256) {       // 16B chunks: 2 pl x 128 r x 8
        int pl = f >> 10, rem = f & 1023;
        int r = rem >> 3, c8 = (rem & 7) * 8;
        const __half* src = (pl ? g_Ml : g_Mh) +
            ((size_t)(kc0 + (r >> 6)) * 64 + (r & 63)) * 64 + c8;
        *reinterpret_cast<float4*>(&(pl ? Mls : Mhs)[r * 72 + c8]) =
            *reinterpret_cast<const float4*>(src);
    }
    if (tid < 128) Ts[tid] = g_t[kc0 * 64 + tid];
    if (tid < 2) cK[tid] = g_c[kc0 + tid];
    __syncthreads();

    for (int tile = 0; tile < BATCH / 64; tile++) {
        const int b0 = tile * 64;
        float acc[2][4][4];
#pragma unroll
        for (int i = 0; i < 2; i++)
#pragma unroll
            for (int j = 0; j < 4; j++)
#pragma unroll
                for (int q = 0; q < 4; q++) acc[i][j][q] = 0.f;

        auto loadE = [&](int sb, int k0) {
#pragma unroll
            for (int q = 0; q < 2; q++) {
                int u = tid + q * 256;
                int pl = u >> 8, rem = u & 255;
                int r = rem >> 2, c8 = (rem & 3) * 8;
                cpa16(&(pl ? Els : Ehs)[(sb * 64 + r) * 40 + c8],
                      (pl ? g_encl : g_ench) + (size_t)(b0 + r) * 64 + k0 + c8);
            }
        };
        loadE(0, 0); cp_commit();
        for (int s = 0; s < 2; s++) {
            if (s == 0) { loadE(1, 32); cp_commit(); cp_wait<1>(); }
            else cp_wait<0>();
            __syncthreads();
#pragma unroll
            for (int kk = 0; kk < 32; kk += 16) {
                uint32_t bh[4][2], bl[4][2];
#pragma unroll
                for (int ni = 0; ni < 4; ni++) {
                    const int rb = (wn * 32 + ni * 8 + gid) * 72 + s * 32 + kk + 2 * tig;
                    bh[ni][0] = ldh32(&Mhs[rb]); bh[ni][1] = ldh32(&Mhs[rb + 8]);
                    bl[ni][0] = ldh32(&Mls[rb]); bl[ni][1] = ldh32(&Mls[rb + 8]);
                }
#pragma unroll
                for (int mi = 0; mi < 2; mi++) {
                    const int ra = (s * 64 + wm * 32 + mi * 16 + gid) * 40 + kk + 2 * tig;
                    uint32_t ah[4], al[4];
                    ah[0] = ldh32(&Ehs[ra]);     ah[1] = ldh32(&Ehs[ra + 320]);
                    ah[2] = ldh32(&Ehs[ra + 8]); ah[3] = ldh32(&Ehs[ra + 328]);
                    al[0] = ldh32(&Els[ra]);     al[1] = ldh32(&Els[ra + 320]);
                    al[2] = ldh32(&Els[ra + 8]); al[3] = ldh32(&Els[ra + 328]);
#pragma unroll
                    for (int ni = 0; ni < 4; ni++) {
                        mma16(acc[mi][ni], ah, bl[ni]);
                        mma16(acc[mi][ni], al, bh[ni]);
                        mma16(acc[mi][ni], ah, bh[ni]);
                    }
                }
            }
            __syncthreads();
        }
        // quad partials: each warp sums its 32 cols per row
#pragma unroll
        for (int mi = 0; mi < 2; mi++)
#pragma unroll
            for (int h = 0; h < 2; h++) {
                float q = 0.f;
#pragma unroll
                for (int ni = 0; ni < 4; ni++) {
                    const int col = wn * 32 + ni * 8 + 2 * tig;
                    float z0 = acc[mi][ni][2 * h] - Ts[col];
                    float z1 = acc[mi][ni][2 * h + 1] - Ts[col + 1];
                    q = fmaf(z0, z0, fmaf(z1, z1, q));
                }
                q += __shfl_xor_sync(0xffffffffu, q, 1);
                q += __shfl_xor_sync(0xffffffffu, q, 2);
                if (tig == 0) sP[(wm * 32 + mi * 16 + gid + 8 * h) * 4 + wn] = q;
            }
        __syncthreads();
        if (tid < 128) {
            const int row = tid & 63, c = tid >> 6;
            float lp = cK[c] - 0.5f * (sP[row * 4 + 2 * c] + sP[row * 4 + 2 * c + 1]);
            g_lpT[(size_t)(kc0 + c) * BATCH + b0 + row] = lp;
        }
        __syncthreads();
    }
}

// ---------------- transpose lpT -> out_lp [B][K] ----------------------------
__global__ void transpose_lp(float* __restrict__ out_lp) {
    __shared__ float t[32][33];
    const int bx = blockIdx.x * 32, ky = blockIdx.y * 32;
    const int tx = threadIdx.x, ty = threadIdx.y;
#pragma unroll
    for (int i = 0; i < 4; i++)
        t[ty + 8 * i][tx] = g_lpT[(size_t)(ky + ty + 8 * i) * BATCH + bx + tx];
    __syncthreads();
#pragma unroll
    for (int i = 0; i < 4; i++)
        out_lp[(size_t)(bx + ty + 8 * i) * KC + ky + tx] = t[tx][ty + 8 * i];
}

// ---------------- argmax (first-max-wins) -----------------------------------
__global__ void argmax_kernel(const float* __restrict__ lp, float* __restrict__ out_idx) {
    const int row = blockIdx.x * 8 + (threadIdx.x >> 5);
    const int lane = threadIdx.x & 31;
    float best = -3.4e38f; int bi = 0;
#pragma unroll
    for (int q = 0; q < 2; q++) {
        const int kk = lane * 4 + q * 128;
        float4 v = *reinterpret_cast<const float4*>(lp + (size_t)row * KC + kk);
        if (v.x > best) { best = v.x; bi = kk; }
        if (v.y > best) { best = v.y; bi = kk + 1; }
        if (v.z > best) { best = v.z; bi = kk + 2; }
        if (v.w > best) { best = v.w; bi = kk + 3; }
    }
#pragma unroll
    for (int o = 16; o; o >>= 1) {
        float ov = __shfl_xor_sync(0xffffffffu, best, o);
        int oi = __shfl_xor_sync(0xffffffffu, bi, o);
        if (ov > best || (ov == best && oi < bi)) { best = ov; bi = oi; }
    }
    if (lane == 0) { g_idx[row] = bi; out_idx[row] = (float)bi; }
}

// ---------------- sample = means[idx] + L_raw[idx] @ noise ------------------
__global__ void sample_kernel(const float* __restrict__ means,
                              const float* __restrict__ noise) {
    __shared__ float sn[EMB];
    const int bb = blockIdx.x;
    const int i = threadIdx.x;
    sn[i] = noise[(size_t)bb * EMB + i];
    __syncthreads();
    const int k = g_idx[bb];
    const float* Lr = g_Lraw + (size_t)k * EMB * EMB + i * EMB;
    float s = means[k * EMB + i];
    for (int j = 0; j <= i; j++) s = fmaf(Lr[j], sn[j], s);
    __half h, l;
    split_h(s, h, l);
    g_smph[(size_t)bb * EMB + i] = h;
    g_smpl[(size_t)bb * EMB + i] = l;
}

// ---------------- launch ----------------------------------------------------
extern "C" void kernel_launch(void* const* d_in, const int* in_sizes, int n_in,
                              void* d_out, int out_size) {
    const float* x     = (const float*)d_in[0];
    const float* noise = (const float*)d_in[1];
    const float* eW1 = (const float*)d_in[2];  const float* eb1 = (const float*)d_in[3];
    const float* eW2 = (const float*)d_in[4];  const float* eb2 = (const float*)d_in[5];
    const float* eW3 = (const float*)d_in[6];  const float* eb3 = (const float*)d_in[7];
    const float* dW1 = (const float*)d_in[8];  const float* db1 = (const float*)d_in[9];
    const float* dW2 = (const float*)d_in[10]; const float* db2 = (const float*)d_in[11];
    const float* dW3 = (const float*)d_in[12]; const float* db3 = (const float*)d_in[13];
    const float* means = (const float*)d_in[14];
    const float* sizes = (const float*)d_in[15];
    const float* cov   = (const float*)d_in[16];

    float* out = (float*)d_out;
    float* out_dec = out;
    float* out_lp  = out + (size_t)BATCH * INDIM;
    float* out_idx = out + (size_t)BATCH * (INDIM + KC);

    __half *xh, *xl, *h1h, *h1l, *h2h, *h2l, *ench, *encl, *smph, *smpl;
    __half *eW1h, *eW1l, *eW2h, *eW2l, *eW3h, *eW3l, *dW1h, *dW1l, *dW2h, *dW2l, *dW3h, *dW3l;
    cudaGetSymbolAddress((void**)&xh, g_xh);   cudaGetSymbolAddress((void**)&xl, g_xl);
    cudaGetSymbolAddress((void**)&h1h, g_h1h); cudaGetSymbolAddress((void**)&h1l, g_h1l);
    cudaGetSymbolAddress((void**)&h2h, g_h2h); cudaGetSymbolAddress((void**)&h2l, g_h2l);
    cudaGetSymbolAddress((void**)&ench, g_ench); cudaGetSymbolAddress((void**)&encl, g_encl);
    cudaGetSymbolAddress((void**)&smph, g_smph); cudaGetSymbolAddress((void**)&smpl, g_smpl);
    cudaGetSymbolAddress((void**)&eW1h, g_eW1h); cudaGetSymbolAddress((void**)&eW1l, g_eW1l);
    cudaGetSymbolAddress((void**)&eW2h, g_eW2h); cudaGetSymbolAddress((void**)&eW2l, g_eW2l);
    cudaGetSymbolAddress((void**)&eW3h, g_eW3h); cudaGetSymbolAddress((void**)&eW3l, g_eW3l);
    cudaGetSymbolAddress((void**)&dW1h, g_dW1h); cudaGetSymbolAddress((void**)&dW1l, g_dW1l);
    cudaGetSymbolAddress((void**)&dW2h, g_dW2h); cudaGetSymbolAddress((void**)&dW2l, g_dW2l);
    cudaGetSymbolAddress((void**)&dW3h, g_dW3h); cudaGetSymbolAddress((void**)&dW3l, g_dW3l);

    // dynamic smem sizes (bytes)
    const int s33 = (2 * 2 * 128 * 40 + 2 * 2 * 64 * 40) * 2;  // 61440
    const int s13 = (2 * 2 * 64 * 40 + 2 * 2 * 64 * 40) * 2;   // 40960
    const int s22 = (2 * 1 * 128 * 40 + 2 * 2 * 64 * 40) * 2;  // 40960
    const int sq  = 2 * 128 * 72 * 2 + 2 * 2 * 64 * 40 * 2 + (128 + 256 + 2) * 4;  // 58888
    cudaFuncSetAttribute(gemm_h<2, 3, 1, 1>, cudaFuncAttributeMaxDynamicSharedMemorySize, s33);
    cudaFuncSetAttribute(gemm_h<1, 3, 0, 1>, cudaFuncAttributeMaxDynamicSharedMemorySize, s13);
    cudaFuncSetAttribute(gemm_h<2, 2, 1, 1>, cudaFuncAttributeMaxDynamicSharedMemorySize, s22);
    cudaFuncSetAttribute(gemm_h<2, 2, 0, 0>, cudaFuncAttributeMaxDynamicSharedMemorySize, s22);
    cudaFuncSetAttribute(quad_kernel, cudaFuncAttributeMaxDynamicSharedMemorySize, sq);

    // pre-split x + weights into fp16 hi/lo planes
    split16<<<(BATCH * INDIM / 2 + 255) / 256, 256>>>(x, xh, xl, BATCH * INDIM);
    split16<<<(DENSE * INDIM / 2 + 255) / 256, 256>>>(eW1, eW1h, eW1l, DENSE * INDIM);
    split16<<<(DENSE * DENSE / 2 + 255) / 256, 256>>>(eW2, eW2h, eW2l, DENSE * DENSE);
    split16<<<(EMB * DENSE / 2 + 255) / 256, 256>>>(eW3, eW3h, eW3l, EMB * DENSE);
    split16<<<(DENSE * EMB / 2 + 255) / 256, 256>>>(dW1, dW1h, dW1l, DENSE * EMB);
    split16<<<(DENSE * DENSE / 2 + 255) / 256, 256>>>(dW2, dW2h, dW2l, DENSE * DENSE);
    split16<<<(INDIM * DENSE / 2 + 255) / 256, 256>>>(dW3, dW3h, dW3l, INDIM * DENSE);

    prep_clusters<<<KC, EMB>>>(cov, means, sizes);

    // encoder (full 3-term: argmax-critical path)
    gemm_h<2, 3, 1, 1><<<dim3(DENSE / 64, BATCH / 128), 256, s33>>>(
        xh, xl, eW1h, eW1l, eb1, h1h, h1l, nullptr, BATCH, DENSE, INDIM);
    gemm_h<2, 3, 1, 1><<<dim3(DENSE / 64, BATCH / 128), 256, s33>>>(
        h1h, h1l, eW2h, eW2l, eb2, h2h, h2l, nullptr, BATCH, DENSE, DENSE);
    gemm_h<1, 3, 0, 1><<<dim3(EMB / 64, BATCH / 64), 256, s13>>>(
        h2h, h2l, eW3h, eW3l, eb3, ench, encl, nullptr, BATCH, EMB, DENSE);

    // quantize (3-term)
    quad_kernel<<<KC / 2, 256, sq>>>();
    transpose_lp<<<dim3(BATCH / 32, KC / 32), dim3(32, 8)>>>(out_lp);
    argmax_kernel<<<BATCH / 8, 256>>>(out_lp, out_idx);
    sample_kernel<<<BATCH, EMB>>>(means, noise);

    // decoder (2-term: A-lo dropped; ~2^-11 relative, ample vs 1e-3)
    gemm_h<2, 2, 1, 1><<<dim3(DENSE / 64, BATCH / 128), 256, s22>>>(
        smph, nullptr, dW1h, dW1l, db1, h1h, h1l, nullptr, BATCH, DENSE, EMB);
    gemm_h<2, 2, 1, 1><<<dim3(DENSE / 64, BATCH / 128), 256, s22>>>(
        h1h, nullptr, dW2h, dW2l, db2, h2h, h2l, nullptr, BATCH, DENSE, DENSE);
    gemm_h<2, 2, 0, 0><<<dim3(INDIM / 64, BATCH / 128), 256, s22>>>(
        h2h, nullptr, dW3h, dW3l, db3, nullptr, nullptr, out_dec, BATCH, INDIM, DENSE);
}

// round 10
// speedup vs baseline: 2.1905x; 1.0759x over previous
#include <cuda_runtime.h>
#include <cuda_fp16.h>
#include <math.h>
#include <stdint.h>

#define BATCH 8192
#define INDIM 512
#define EMB   64
#define KC    256
#define DENSE 1152

// ---------------- scratch globals: fp16 hi/lo planes ------------------------
__device__ __half g_xh [BATCH * INDIM],  g_xl [BATCH * INDIM];
__device__ __half g_h1h[BATCH * DENSE],  g_h1l[BATCH * DENSE];
__device__ __half g_h2h[BATCH * DENSE],  g_h2l[BATCH * DENSE];
__device__ __half g_ench[BATCH * EMB],   g_encl[BATCH * EMB];
__device__ __half g_smph[BATCH * EMB],   g_smpl[BATCH * EMB];
__device__ __half g_eW1h[DENSE * INDIM], g_eW1l[DENSE * INDIM];
__device__ __half g_eW2h[DENSE * DENSE], g_eW2l[DENSE * DENSE];
__device__ __half g_eW3h[EMB * DENSE],   g_eW3l[EMB * DENSE];
__device__ __half g_dW1h[DENSE * EMB],   g_dW1l[DENSE * EMB];
__device__ __half g_dW2h[DENSE * DENSE], g_dW2l[DENSE * DENSE];
__device__ __half g_dW3h[INDIM * DENSE], g_dW3l[INDIM * DENSE];
__device__ __half g_Mh[KC * EMB * EMB],  g_Ml[KC * EMB * EMB];
__device__ float g_Lraw[KC * EMB * EMB];
__device__ float g_t[KC * EMB];
__device__ float g_c[KC];
__device__ float g_lpT[KC * BATCH];
__device__ int   g_idx[BATCH];

__device__ __forceinline__ float selu_f(float x) {
    const float alpha = 1.6732632423543772f;
    const float scale = 1.0507009873554805f;
    return scale * (x > 0.f ? x : alpha * expm1f(x));
}

// ---------------- ptx helpers ----------------------------------------------
__device__ __forceinline__ void cpa16(void* d, const void* s) {
    uint32_t a = (uint32_t)__cvta_generic_to_shared(d);
    asm volatile("cp.async.cg.shared.global [%0],[%1],16;" :: "r"(a), "l"(s));
}
__device__ __forceinline__ void cp_commit() { asm volatile("cp.async.commit_group;"); }
template <int N> __device__ __forceinline__ void cp_wait() {
    asm volatile("cp.async.wait_group %0;" :: "n"(N));
}
__device__ __forceinline__ void split_h(float v, __half& h, __half& l) {
    h = __float2half_rn(v);
    l = __float2half_rn(v - __half2float(h));
}
__device__ __forceinline__ void mma16(float* c, const uint32_t* a, const uint32_t* b) {
    asm volatile(
        "mma.sync.aligned.m16n8k16.row.col.f32.f16.f16.f32 "
        "{%0,%1,%2,%3},{%4,%5,%6,%7},{%8,%9},{%0,%1,%2,%3};"
        : "+f"(c[0]), "+f"(c[1]), "+f"(c[2]), "+f"(c[3])
        : "r"(a[0]), "r"(a[1]), "r"(a[2]), "r"(a[3]), "r"(b[0]), "r"(b[1]));
}
// ldmatrix x4: loads 4 8x8 b16 tiles; per-thread addr selects row of tile lane/8
__device__ __forceinline__ void ldsm4p(uint32_t* r, const void* p) {
    uint32_t a = (uint32_t)__cvta_generic_to_shared(p);
    asm volatile("ldmatrix.sync.aligned.m8n8.x4.shared.b16 {%0,%1,%2,%3}, [%4];"
                 : "=r"(r[0]), "=r"(r[1]), "=r"(r[2]), "=r"(r[3]) : "r"(a));
}

// ---------------- split fp32 matrix -> fp16 hi/lo planes --------------------
__global__ void split16(const float* __restrict__ src,
                        __half* __restrict__ dh, __half* __restrict__ dl, int n) {
    int i = (blockIdx.x * blockDim.x + threadIdx.x) * 2;
    if (i < n) {
        float2 v = *reinterpret_cast<const float2*>(src + i);
        __half h0, l0, h1, l1;
        split_h(v.x, h0, l0);
        split_h(v.y, h1, l1);
        *reinterpret_cast<__half2*>(dh + i) = __halves2half2(h0, h1);
        *reinterpret_cast<__half2*>(dl + i) = __halves2half2(l0, l1);
    }
}

// ---------------- cluster prep ----------------------------------------------
__device__ void chol64(float (*A)[EMB + 1], float (*L)[EMB + 1], int tid) {
    __shared__ float sdiag;
    for (int j = 0; j < EMB; j++) {
        if (tid == j) {
            float s = A[j][j];
            for (int q = 0; q < j; q++) s -= L[j][q] * L[j][q];
            float d = sqrtf(fmaxf(s, 1e-30f));
            L[j][j] = d; sdiag = d;
        }
        __syncthreads();
        if (tid > j) {
            float s = A[tid][j];
            for (int q = 0; q < j; q++) s -= L[tid][q] * L[j][q];
            L[tid][j] = s / sdiag;
        }
        __syncthreads();
    }
}

__global__ void prep_clusters(const float* __restrict__ cov,
                              const float* __restrict__ means,
                              const float* __restrict__ sizes) {
    __shared__ float sA[EMB][EMB + 1];
    __shared__ float sL[EMB][EMB + 1];
    __shared__ float smu[EMB];
    const int k = blockIdx.x;
    const int tid = threadIdx.x;
    const float* Ck = cov + (size_t)k * EMB * EMB;

    for (int i = 0; i < EMB; i++) { sA[i][tid] = Ck[i * EMB + tid]; sL[i][tid] = 0.f; }
    __syncthreads();
    sA[tid][tid] += 0.005f;
    __syncthreads();
    chol64(sA, sL, tid);

    if (tid == 0) {
        float ld = 0.f;
        for (int j = 0; j < EMB; j++) ld += logf(sL[j][j]);
        g_c[k] = logf(sizes[k]) - 0.5f * (EMB * 1.8378770664093453f) - ld;
    }

    for (int i = 0; i < EMB; i++) sA[i][tid] = 0.f;
    __syncthreads();
    {
        const int c = tid;
        for (int i = c; i < EMB; i++) {
            float s = (i == c) ? 1.f : 0.f;
            for (int q = c; q < i; q++) s -= sL[i][q] * sA[q][c];
            sA[i][c] = s / sL[i][i];
        }
    }
    __syncthreads();
    for (int r = 0; r < EMB; r++) {
        __half h, l;
        split_h(sA[r][tid], h, l);
        g_Mh[((size_t)k * EMB + r) * EMB + tid] = h;
        g_Ml[((size_t)k * EMB + r) * EMB + tid] = l;
    }
    smu[tid] = means[k * EMB + tid];
    __syncthreads();
    {
        float s = 0.f;
        for (int j = 0; j < EMB; j++) s += sA[tid][j] * smu[j];
        g_t[k * EMB + tid] = s;
    }
    __syncthreads();

    for (int i = 0; i < EMB; i++) { sA[i][tid] = Ck[i * EMB + tid]; sL[i][tid] = 0.f; }
    __syncthreads();
    chol64(sA, sL, tid);
    for (int r = 0; r < EMB; r++)
        g_Lraw[(size_t)k * EMB * EMB + r * EMB + tid] = sL[r][tid];
}

// ---------------- split-fp16 tensor GEMM (mma.sync + ldmatrix), K-chunk 32 --
// C = act(A @ W^T + bias).  Block BM=64*MI x 64; 8 warps: 4m x 2n.
// TERMS=3: acc = ah*bh + ah*bl + al*bh.  TERMS=2: acc = ah*bh + ah*bl.
// Smem rows stride 40 halfs (80B): LDSM row reads hit distinct bank groups.
template <int MI, int TERMS, int ACT, int SPLIT_OUT>
__global__ __launch_bounds__(256) void gemm_h(
    const __half* __restrict__ Ah, const __half* __restrict__ Al,
    const __half* __restrict__ Wh, const __half* __restrict__ Wl,
    const float* __restrict__ bias,
    __half* __restrict__ Ch, __half* __restrict__ Cl, float* __restrict__ Cf,
    int M, int N, int K)
{
    constexpr int BM = 64 * MI;
    constexpr int PA = (TERMS == 3) ? 2 : 1;
    extern __shared__ __half sh[];
    __half* SA = sh;                       // [2][PA][BM*40]
    __half* SW = sh + 2 * PA * BM * 40;    // [2][2][64*40]
    const int tid = threadIdx.x;
    const int lane = tid & 31, w = tid >> 5;
    const int gid = lane >> 2, tig = lane & 3;
    const int wm = w >> 1, wn = w & 1;
    const int m0 = blockIdx.y * BM, n0 = blockIdx.x * 64;
    // ldmatrix per-thread offsets
    const int rr = lane & 7, mq = lane >> 3;
    const int aro = rr + 8 * (mq & 1), aco = 8 * (mq >> 1);   // A: rows/cols
    const int bro = rr + 8 * (mq >> 1), bco = 8 * (mq & 1);   // B: n-rows/k-cols

    float acc[MI][4][4];
#pragma unroll
    for (int i = 0; i < MI; i++)
#pragma unroll
        for (int j = 0; j < 4; j++)
#pragma unroll
            for (int q = 0; q < 4; q++) acc[i][j][q] = 0.f;

    auto fill = [&](int s, int k0) {
#pragma unroll
        for (int q = 0; q < PA * BM / 64; q++) {
            int u = tid + q * 256;
            int pl = u / (BM * 4), rem = u % (BM * 4);
            int r = rem >> 2, c8 = (rem & 3) * 8;
            cpa16(&SA[((size_t)(s * PA + pl) * BM + r) * 40 + c8],
                  (pl ? Al : Ah) + (size_t)(m0 + r) * K + k0 + c8);
        }
#pragma unroll
        for (int q = 0; q < 2; q++) {
            int u = tid + q * 256;
            int pl = u >> 8, rem = u & 255;
            int r = rem >> 2, c8 = (rem & 3) * 8;
            cpa16(&SW[((size_t)(s * 2 + pl) * 64 + r) * 40 + c8],
                  (pl ? Wl : Wh) + (size_t)(n0 + r) * K + k0 + c8);
        }
    };

    const int nst = K / 32;
    fill(0, 0); cp_commit();
    for (int s = 0; s < nst; s++) {
        if (s + 1 < nst) { fill((s + 1) & 1, (s + 1) * 32); cp_commit(); cp_wait<1>(); }
        else cp_wait<0>();
        __syncthreads();
        const int bs = s & 1;
#pragma unroll
        for (int kk = 0; kk < 32; kk += 16) {
            uint32_t bh[4][2], bl[4][2];
#pragma unroll
            for (int p = 0; p < 2; p++) {
                uint32_t r4[4];
                const int nb = wn * 32 + p * 16 + bro;
                ldsm4p(r4, &SW[((bs * 2 + 0) * 64 + nb) * 40 + kk + bco]);
                bh[2 * p][0] = r4[0]; bh[2 * p][1] = r4[1];
                bh[2 * p + 1][0] = r4[2]; bh[2 * p + 1][1] = r4[3];
                ldsm4p(r4, &SW[((bs * 2 + 1) * 64 + nb) * 40 + kk + bco]);
                bl[2 * p][0] = r4[0]; bl[2 * p][1] = r4[1];
                bl[2 * p + 1][0] = r4[2]; bl[2 * p + 1][1] = r4[3];
            }
#pragma unroll
            for (int mi = 0; mi < MI; mi++) {
                const int rowa = wm * 16 * MI + mi * 16 + aro;
                uint32_t ah[4];
                ldsm4p(ah, &SA[((bs * PA + 0) * BM + rowa) * 40 + kk + aco]);
                if (TERMS == 3) {
                    uint32_t al[4];
                    ldsm4p(al, &SA[((bs * PA + 1) * BM + rowa) * 40 + kk + aco]);
#pragma unroll
                    for (int ni = 0; ni < 4; ni++) {
                        mma16(acc[mi][ni], ah, bl[ni]);
                        mma16(acc[mi][ni], al, bh[ni]);
                        mma16(acc[mi][ni], ah, bh[ni]);
                    }
                } else {
#pragma unroll
                    for (int ni = 0; ni < 4; ni++) {
                        mma16(acc[mi][ni], ah, bl[ni]);
                        mma16(acc[mi][ni], ah, bh[ni]);
                    }
                }
            }
        }
        __syncthreads();
    }

#pragma unroll
    for (int mi = 0; mi < MI; mi++)
#pragma unroll
        for (int ni = 0; ni < 4; ni++) {
            const int row = m0 + wm * 16 * MI + mi * 16 + gid;
            const int col = n0 + wn * 32 + ni * 8 + 2 * tig;
            const float bv0 = __ldg(bias + col), bv1 = __ldg(bias + col + 1);
            float v0 = acc[mi][ni][0] + bv0, v1 = acc[mi][ni][1] + bv1;
            float v2 = acc[mi][ni][2] + bv0, v3 = acc[mi][ni][3] + bv1;
            if (ACT) { v0 = selu_f(v0); v1 = selu_f(v1); v2 = selu_f(v2); v3 = selu_f(v3); }
            if (SPLIT_OUT) {
                __half h0, l0, h1, l1;
                split_h(v0, h0, l0); split_h(v1, h1, l1);
                *reinterpret_cast<__half2*>(Ch + (size_t)row * N + col) = __halves2half2(h0, h1);
                *reinterpret_cast<__half2*>(Cl + (size_t)row * N + col) = __halves2half2(l0, l1);
                split_h(v2, h0, l0); split_h(v3, h1, l1);
                *reinterpret_cast<__half2*>(Ch + (size_t)(row + 8) * N + col) = __halves2half2(h0, h1);
                *reinterpret_cast<__half2*>(Cl + (size_t)(row + 8) * N + col) = __halves2half2(l0, l1);
            } else {
                *reinterpret_cast<float2*>(Cf + (size_t)row * N + col) = make_float2(v0, v1);
                *reinterpret_cast<float2*>(Cf + (size_t)(row + 8) * N + col) = make_float2(v2, v3);
            }
        }
}

// ---------------- fused quad/log_prob: 2 clusters/block, ldmatrix ------------
// M (128 rows, hi/lo, stride 72 halfs) resident; enc streamed (stride 40).
// 8 warps: 2 m-warps x 4 n-warps.
__global__ __launch_bounds__(256) void quad_kernel() {
    extern __shared__ __half qsh[];
    __half* Mhs = qsh;                   // [128][72]
    __half* Mls = qsh + 128 * 72;
    __half* Ehs = qsh + 2 * 128 * 72;    // [2][64*40]
    __half* Els = Ehs + 2 * 64 * 40;
    float*  Ts  = (float*)(Els + 2 * 64 * 40);  // [128]
    float*  sP  = Ts + 128;                     // [64][4]
    float*  cK  = sP + 256;                     // [2]
    const int tid = threadIdx.x;
    const int lane = tid & 31, w = tid >> 5;
    const int gid = lane >> 2, tig = lane & 3;
    const int wn = w & 3, wm = w >> 2;
    const int kc0 = blockIdx.x * 2;
    const int rr = lane & 7, mq = lane >> 3;
    const int aro = rr + 8 * (mq & 1), aco = 8 * (mq >> 1);
    const int bro = rr + 8 * (mq >> 1), bco = 8 * (mq & 1);

    for (int f = tid; f < 2048; f += 256) {       // 16B chunks: 2 pl x 128 r x 8
        int pl = f >> 10, rem = f & 1023;
        int r = rem >> 3, c8 = (rem & 7) * 8;
        const __half* src = (pl ? g_Ml : g_Mh) +
            ((size_t)(kc0 + (r >> 6)) * 64 + (r & 63)) * 64 + c8;
        *reinterpret_cast<float4*>(&(pl ? Mls : Mhs)[r * 72 + c8]) =
            *reinterpret_cast<const float4*>(src);
    }
    if (tid < 128) Ts[tid] = g_t[kc0 * 64 + tid];
    if (tid < 2) cK[tid] = g_c[kc0 + tid];
    __syncthreads();

    for (int tile = 0; tile < BATCH / 64; tile++) {
        const int b0 = tile * 64;
        float acc[2][4][4];
#pragma unroll
        for (int i = 0; i < 2; i++)
#pragma unroll
            for (int j = 0; j < 4; j++)
#pragma unroll
                for (int q = 0; q < 4; q++) acc[i][j][q] = 0.f;

        auto loadE = [&](int sb, int k0) {
#pragma unroll
            for (int q = 0; q < 2; q++) {
                int u = tid + q * 256;
                int pl = u >> 8, rem = u & 255;
                int r = rem >> 2, c8 = (rem & 3) * 8;
                cpa16(&(pl ? Els : Ehs)[(sb * 64 + r) * 40 + c8],
                      (pl ? g_encl : g_ench) + (size_t)(b0 + r) * 64 + k0 + c8);
            }
        };
        loadE(0, 0); cp_commit();
        for (int s = 0; s < 2; s++) {
            if (s == 0) { loadE(1, 32); cp_commit(); cp_wait<1>(); }
            else cp_wait<0>();
            __syncthreads();
#pragma unroll
            for (int kk = 0; kk < 32; kk += 16) {
                uint32_t bh[4][2], bl[4][2];
#pragma unroll
                for (int p = 0; p < 2; p++) {
                    uint32_t r4[4];
                    const int nb = wn * 32 + p * 16 + bro;
                    ldsm4p(r4, &Mhs[nb * 72 + s * 32 + kk + bco]);
                    bh[2 * p][0] = r4[0]; bh[2 * p][1] = r4[1];
                    bh[2 * p + 1][0] = r4[2]; bh[2 * p + 1][1] = r4[3];
                    ldsm4p(r4, &Mls[nb * 72 + s * 32 + kk + bco]);
                    bl[2 * p][0] = r4[0]; bl[2 * p][1] = r4[1];
                    bl[2 * p + 1][0] = r4[2]; bl[2 * p + 1][1] = r4[3];
                }
#pragma unroll
                for (int mi = 0; mi < 2; mi++) {
                    const int ra = s * 64 + wm * 32 + mi * 16 + aro;
                    uint32_t ah[4], al[4];
                    ldsm4p(ah, &Ehs[ra * 40 + kk + aco]);
                    ldsm4p(al, &Els[ra * 40 + kk + aco]);
#pragma unroll
                    for (int ni = 0; ni < 4; ni++) {
                        mma16(acc[mi][ni], ah, bl[ni]);
                        mma16(acc[mi][ni], al, bh[ni]);
                        mma16(acc[mi][ni], ah, bh[ni]);
                    }
                }
            }
            __syncthreads();
        }
        // quad partials: each warp sums its 32 cols per row
#pragma unroll
        for (int mi = 0; mi < 2; mi++)
#pragma unroll
            for (int h = 0; h < 2; h++) {
                float q = 0.f;
#pragma unroll
                for (int ni = 0; ni < 4; ni++) {
                    const int col = wn * 32 + ni * 8 + 2 * tig;
                    float z0 = acc[mi][ni][2 * h] - Ts[col];
                    float z1 = acc[mi][ni][2 * h + 1] - Ts[col + 1];
                    q = fmaf(z0, z0, fmaf(z1, z1, q));
                }
                q += __shfl_xor_sync(0xffffffffu, q, 1);
                q += __shfl_xor_sync(0xffffffffu, q, 2);
                if (tig == 0) sP[(wm * 32 + mi * 16 + gid + 8 * h) * 4 + wn] = q;
            }
        __syncthreads();
        if (tid < 128) {
            const int row = tid & 63, c = tid >> 6;
            float lp = cK[c] - 0.5f * (sP[row * 4 + 2 * c] + sP[row * 4 + 2 * c + 1]);
            g_lpT[(size_t)(kc0 + c) * BATCH + b0 + row] = lp;
        }
        __syncthreads();
    }
}

// ---------------- transpose lpT -> out_lp [B][K] ----------------------------
__global__ void transpose_lp(float* __restrict__ out_lp) {
    __shared__ float t[32][33];
    const int bx = blockIdx.x * 32, ky = blockIdx.y * 32;
    const int tx = threadIdx.x, ty = threadIdx.y;
#pragma unroll
    for (int i = 0; i < 4; i++)
        t[ty + 8 * i][tx] = g_lpT[(size_t)(ky + ty + 8 * i) * BATCH + bx + tx];
    __syncthreads();
#pragma unroll
    for (int i = 0; i < 4; i++)
        out_lp[(size_t)(bx + ty + 8 * i) * KC + ky + tx] = t[tx][ty + 8 * i];
}

// ---------------- argmax (first-max-wins) -----------------------------------
__global__ void argmax_kernel(const float* __restrict__ lp, float* __restrict__ out_idx) {
    const int row = blockIdx.x * 8 + (threadIdx.x >> 5);
    const int lane = threadIdx.x & 31;
    float best = -3.4e38f; int bi = 0;
#pragma unroll
    for (int q = 0; q < 2; q++) {
        const int kk = lane * 4 + q * 128;
        float4 v = *reinterpret_cast<const float4*>(lp + (size_t)row * KC + kk);
        if (v.x > best) { best = v.x; bi = kk; }
        if (v.y > best) { best = v.y; bi = kk + 1; }
        if (v.z > best) { best = v.z; bi = kk + 2; }
        if (v.w > best) { best = v.w; bi = kk + 3; }
    }
#pragma unroll
    for (int o = 16; o; o >>= 1) {
        float ov = __shfl_xor_sync(0xffffffffu, best, o);
        int oi = __shfl_xor_sync(0xffffffffu, bi, o);
        if (ov > best || (ov == best && oi < bi)) { best = ov; bi = oi; }
    }
    if (lane == 0) { g_idx[row] = bi; out_idx[row] = (float)bi; }
}

// ---------------- sample = means[idx] + L_raw[idx] @ noise ------------------
__global__ void sample_kernel(const float* __restrict__ means,
                              const float* __restrict__ noise) {
    __shared__ float sn[EMB];
    const int bb = blockIdx.x;
    const int i = threadIdx.x;
    sn[i] = noise[(size_t)bb * EMB + i];
    __syncthreads();
    const int k = g_idx[bb];
    const float* Lr = g_Lraw + (size_t)k * EMB * EMB + i * EMB;
    float s = means[k * EMB + i];
    for (int j = 0; j <= i; j++) s = fmaf(Lr[j], sn[j], s);
    __half h, l;
    split_h(s, h, l);
    g_smph[(size_t)bb * EMB + i] = h;
    g_smpl[(size_t)bb * EMB + i] = l;
}

// ---------------- launch ----------------------------------------------------
extern "C" void kernel_launch(void* const* d_in, const int* in_sizes, int n_in,
                              void* d_out, int out_size) {
    const float* x     = (const float*)d_in[0];
    const float* noise = (const float*)d_in[1];
    const float* eW1 = (const float*)d_in[2];  const float* eb1 = (const float*)d_in[3];
    const float* eW2 = (const float*)d_in[4];  const float* eb2 = (const float*)d_in[5];
    const float* eW3 = (const float*)d_in[6];  const float* eb3 = (const float*)d_in[7];
    const float* dW1 = (const float*)d_in[8];  const float* db1 = (const float*)d_in[9];
    const float* dW2 = (const float*)d_in[10]; const float* db2 = (const float*)d_in[11];
    const float* dW3 = (const float*)d_in[12]; const float* db3 = (const float*)d_in[13];
    const float* means = (const float*)d_in[14];
    const float* sizes = (const float*)d_in[15];
    const float* cov   = (const float*)d_in[16];

    float* out = (float*)d_out;
    float* out_dec = out;
    float* out_lp  = out + (size_t)BATCH * INDIM;
    float* out_idx = out + (size_t)BATCH * (INDIM + KC);

    __half *xh, *xl, *h1h, *h1l, *h2h, *h2l, *ench, *encl, *smph, *smpl;
    __half *eW1h, *eW1l, *eW2h, *eW2l, *eW3h, *eW3l, *dW1h, *dW1l, *dW2h, *dW2l, *dW3h, *dW3l;
    cudaGetSymbolAddress((void**)&xh, g_xh);   cudaGetSymbolAddress((void**)&xl, g_xl);
    cudaGetSymbolAddress((void**)&h1h, g_h1h); cudaGetSymbolAddress((void**)&h1l, g_h1l);
    cudaGetSymbolAddress((void**)&h2h, g_h2h); cudaGetSymbolAddress((void**)&h2l, g_h2l);
    cudaGetSymbolAddress((void**)&ench, g_ench); cudaGetSymbolAddress((void**)&encl, g_encl);
    cudaGetSymbolAddress((void**)&smph, g_smph); cudaGetSymbolAddress((void**)&smpl, g_smpl);
    cudaGetSymbolAddress((void**)&eW1h, g_eW1h); cudaGetSymbolAddress((void**)&eW1l, g_eW1l);
    cudaGetSymbolAddress((void**)&eW2h, g_eW2h); cudaGetSymbolAddress((void**)&eW2l, g_eW2l);
    cudaGetSymbolAddress((void**)&eW3h, g_eW3h); cudaGetSymbolAddress((void**)&eW3l, g_eW3l);
    cudaGetSymbolAddress((void**)&dW1h, g_dW1h); cudaGetSymbolAddress((void**)&dW1l, g_dW1l);
    cudaGetSymbolAddress((void**)&dW2h, g_dW2h); cudaGetSymbolAddress((void**)&dW2l, g_dW2l);
    cudaGetSymbolAddress((void**)&dW3h, g_dW3h); cudaGetSymbolAddress((void**)&dW3l, g_dW3l);

    // dynamic smem sizes (bytes)
    const int s33 = (2 * 2 * 128 * 40 + 2 * 2 * 64 * 40) * 2;  // 61440
    const int s13 = (2 * 2 * 64 * 40 + 2 * 2 * 64 * 40) * 2;   // 40960
    const int s22 = (2 * 1 * 128 * 40 + 2 * 2 * 64 * 40) * 2;  // 40960
    const int sq  = 2 * 128 * 72 * 2 + 2 * 2 * 64 * 40 * 2 + (128 + 256 + 2) * 4;  // 58888
    cudaFuncSetAttribute(gemm_h<2, 3, 1, 1>, cudaFuncAttributeMaxDynamicSharedMemorySize, s33);
    cudaFuncSetAttribute(gemm_h<1, 3, 0, 1>, cudaFuncAttributeMaxDynamicSharedMemorySize, s13);
    cudaFuncSetAttribute(gemm_h<2, 2, 1, 1>, cudaFuncAttributeMaxDynamicSharedMemorySize, s22);
    cudaFuncSetAttribute(gemm_h<2, 2, 0, 0>, cudaFuncAttributeMaxDynamicSharedMemorySize, s22);
    cudaFuncSetAttribute(quad_kernel, cudaFuncAttributeMaxDynamicSharedMemorySize, sq);

    // launches ordered so ncu (-s 5 -c 1) profiles enc1 (launch index 5)
    split16<<<(BATCH * INDIM / 2 + 255) / 256, 256>>>(x, xh, xl, BATCH * INDIM);      // 0
    split16<<<(DENSE * INDIM / 2 + 255) / 256, 256>>>(eW1, eW1h, eW1l, DENSE * INDIM); // 1
    split16<<<(DENSE * DENSE / 2 + 255) / 256, 256>>>(eW2, eW2h, eW2l, DENSE * DENSE); // 2
    split16<<<(EMB * DENSE / 2 + 255) / 256, 256>>>(eW3, eW3h, eW3l, EMB * DENSE);     // 3
    prep_clusters<<<KC, EMB>>>(cov, means, sizes);                                     // 4

    // encoder (full 3-term: argmax-critical path)
    gemm_h<2, 3, 1, 1><<<dim3(DENSE / 64, BATCH / 128), 256, s33>>>(                   // 5
        xh, xl, eW1h, eW1l, eb1, h1h, h1l, nullptr, BATCH, DENSE, INDIM);
    gemm_h<2, 3, 1, 1><<<dim3(DENSE / 64, BATCH / 128), 256, s33>>>(
        h1h, h1l, eW2h, eW2l, eb2, h2h, h2l, nullptr, BATCH, DENSE, DENSE);
    gemm_h<1, 3, 0, 1><<<dim3(EMB / 64, BATCH / 64), 256, s13>>>(
        h2h, h2l, eW3h, eW3l, eb3, ench, encl, nullptr, BATCH, EMB, DENSE);

    // remaining weight splits (needed only by decoder)
    split16<<<(DENSE * EMB / 2 + 255) / 256, 256>>>(dW1, dW1h, dW1l, DENSE * EMB);
    split16<<<(DENSE * DENSE / 2 + 255) / 256, 256>>>(dW2, dW2h, dW2l, DENSE * DENSE);
    split16<<<(INDIM * DENSE / 2 + 255) / 256, 256>>>(dW3, dW3h, dW3l, INDIM * DENSE);

    // quantize (3-term)
    quad_kernel<<<KC / 2, 256, sq>>>();
    transpose_lp<<<dim3(BATCH / 32, KC / 32), dim3(32, 8)>>>(out_lp);
    argmax_kernel<<<BATCH / 8, 256>>>(out_lp, out_idx);
    sample_kernel<<<BATCH, EMB>>>(means, noise);

    // decoder (2-term)
    gemm_h<2, 2, 1, 1><<<dim3(DENSE / 64, BATCH / 128), 256, s22>>>(
        smph, nullptr, dW1h, dW1l, db1, h1h, h1l, nullptr, BATCH, DENSE, EMB);
    gemm_h<2, 2, 1, 1><<<dim3(DENSE / 64, BATCH / 128), 256, s22>>>(
        h1h, nullptr, dW2h, dW2l, db2, h2h, h2l, nullptr, BATCH, DENSE, DENSE);
    gemm_h<2, 2, 0, 0><<<dim3(INDIM / 64, BATCH / 128), 256, s22>>>(
        h2h, nullptr, dW3h, dW3l, db3, nullptr, nullptr, out_dec, BATCH, INDIM, DENSE);
}